// round 8
// baseline (speedup 1.0000x reference)
#include <cuda_runtime.h>
#include <math.h>
#include <stdint.h>

#define NN 1000
#define FF 128
#define TT 4
#define PP 10
#define DD 13
#define EE 20000
#define EAD 16
#define HH 128
#define KK 64
#define NDIM 13000        // N*D
#define IEDGE 169
#define INODE 91
#define WNS 172           // padded Wn row stride (mult of 4)
#define WCPAD 68          // padded Wc smem row stride
#define WPPAD 132         // padded Wp smem row stride
#define NODES8 8
#define CHUNKS 7          // rows per node: 2,2,2,2,2,2,1
#define ASM_SMEM (2*NDIM*4)   // 104000 bytes
#define MAXDEG 512

// ---------------- scratch (device globals; no runtime allocation) ----------------
__device__ __align__(16) float g_m[NN*FF];
__device__ float g_base[NN*FF];
__device__ float g_nh[NN*FF];
__device__ float g_r1[NN*HH];
__device__ float g_r2[NN*HH];
__device__ float g_q1[NN*KK];
__device__ float g_q2[NN*KK];
__device__ __align__(16) float g_Wn[TT*FF*WNS];
__device__ __align__(16) float g_WcT[PP*IEDGE*KK];
__device__ __align__(16) float g_h[EE*2*KK];        // per-edge [h_ij(64) | h_ji(64)]
__device__ __align__(16) float g_blk[(size_t)EE*IEDGE];   // symmetrized blocks B
__device__ float g_nblk[NN*IEDGE];                  // node diagonal blocks
__device__ int   g_off[PP+1];
__device__ int   g_bucket[EE];
__device__ int   g_rowoff[NN+1];
__device__ int   g_rentry[2*EE];                    // e*2 | flag (flag=1 -> this row is dst)

// ---------------- fused change-of-basis weights, coalesced tiled form ----------------
__global__ void __launch_bounds__(192) k_pre_node(const float* __restrict__ Wnode,
                                                  const float* __restrict__ cobn) {
    int t  = blockIdx.x & 3;
    int f0 = (blockIdx.x >> 2) * 16;
    int tid = threadIdx.x;   // 192
    __shared__ float Ws[INODE][17];
    for (int j = tid; j < 16*INODE; j += 192) {
        int f = j / INODE, i = j % INODE;
        Ws[i][f] = Wnode[(t*FF + f0 + f)*INODE + i];
    }
    for (int j = tid; j < 16*3; j += 192)
        g_Wn[(t*FF + f0 + j/3)*WNS + IEDGE + (j % 3)] = 0.f;
    __syncthreads();
    if (tid >= IEDGE) return;
    float acc[16];
    #pragma unroll
    for (int f = 0; f < 16; f++) acc[f] = 0.f;
    for (int i = 0; i < INODE; i++) {
        float cv = cobn[(t*INODE + i)*IEDGE + tid];
        #pragma unroll
        for (int f = 0; f < 16; f++) acc[f] += cv * Ws[i][f];
    }
    #pragma unroll
    for (int f = 0; f < 16; f++) g_Wn[(t*FF + f0 + f)*WNS + tid] = acc[f];
}

__global__ void __launch_bounds__(192) k_pre_edge(const float* __restrict__ Wedge,
                                                  const float* __restrict__ cobe) {
    int p  = blockIdx.x >> 2;
    int k0 = (blockIdx.x & 3) * 16;
    int tid = threadIdx.x;   // 192
    __shared__ float Ws[IEDGE][17];
    for (int j = tid; j < 16*IEDGE; j += 192) {
        int k = j / IEDGE, i = j % IEDGE;
        Ws[i][k] = Wedge[(p*KK + k0 + k)*IEDGE + i];
    }
    __syncthreads();
    if (tid >= IEDGE) return;
    float acc[16];
    #pragma unroll
    for (int k = 0; k < 16; k++) acc[k] = 0.f;
    for (int i = 0; i < IEDGE; i++) {
        float cv = cobe[((size_t)p*IEDGE + i)*IEDGE + tid];
        #pragma unroll
        for (int k = 0; k < 16; k++) acc[k] += cv * Ws[i][k];
    }
    float4* dst = (float4*)&g_WcT[(p*IEDGE + tid)*KK + k0];
    #pragma unroll
    for (int k4 = 0; k4 < 4; k4++)
        dst[k4] = make_float4(acc[4*k4], acc[4*k4+1], acc[4*k4+2], acc[4*k4+3]);
}

// ---------------- node prep: m = nf@Wmsg, base = nf + na@Wattr ----------------
__global__ void k_node_prep(const float* __restrict__ nf, const float* __restrict__ na,
                            const float* __restrict__ Wmsg, const float* __restrict__ Wattr) {
    int n = blockIdx.x;
    int f = threadIdx.x;   // 128
    int gt = n*FF + f;
    __shared__ float row[FF];
    row[f] = nf[gt];
    __syncthreads();
    float a0 = 0.f, a1 = 0.f, a2 = 0.f, a3 = 0.f;
    #pragma unroll 4
    for (int g = 0; g < FF; g += 4) {
        a0 += row[g]   * Wmsg[(g)*FF + f];
        a1 += row[g+1] * Wmsg[(g+1)*FF + f];
        a2 += row[g+2] * Wmsg[(g+2)*FF + f];
        a3 += row[g+3] * Wmsg[(g+3)*FF + f];
    }
    g_m[gt] = (a0 + a1) + (a2 + a3);
    float b = row[f];
    #pragma unroll
    for (int t = 0; t < TT; t++) b += na[n*TT + t] * Wattr[t*FF + f];
    g_base[gt] = b;
}

// ---------------- fused hist + scan + bucket (single CTA, smem counters) ----------------
__global__ void __launch_bounds__(1024) k_index(const int* __restrict__ ei,
                                                const int* __restrict__ et) {
    __shared__ int rc[1024];
    __shared__ int tc[PP], tcur[PP];
    int tid = threadIdx.x;
    rc[tid] = 0;
    if (tid < PP) tc[tid] = 0;
    __syncthreads();
    for (int e = tid; e < EE; e += 1024) {
        atomicAdd(&rc[ei[e]], 1);
        atomicAdd(&rc[ei[EE + e]], 1);
        atomicAdd(&tc[et[e]], 1);
    }
    __syncthreads();
    int v = rc[tid];
    #pragma unroll
    for (int off = 1; off < 1024; off <<= 1) {
        int t = (tid >= off) ? rc[tid - off] : 0;
        __syncthreads();
        rc[tid] += t;
        __syncthreads();
    }
    int excl = rc[tid] - v;
    if (tid < NN) g_rowoff[tid] = excl;
    if (tid == NN - 1) g_rowoff[NN] = rc[tid];
    __syncthreads();
    rc[tid] = excl;
    if (tid == 0) {
        int a = 0;
        for (int p = 0; p < PP; p++) { g_off[p] = a; tcur[p] = a; a += tc[p]; }
        g_off[PP] = a;
    }
    __syncthreads();
    for (int e = tid; e < EE; e += 1024) {
        int p = et[e];
        g_bucket[atomicAdd(&tcur[p], 1)] = e;
        int s = ei[e], d = ei[EE + e];
        g_rentry[atomicAdd(&rc[s], 1)] = e*2;       // row s (col node = dst)
        g_rentry[atomicAdd(&rc[d], 1)] = e*2 + 1;   // row d (col node = src), transposed
    }
}

// ---------------- gather aggregation, chain-free ----------------
__global__ void __launch_bounds__(128) k_gather(const int* __restrict__ ei) {
    int n = blockIdx.x;
    int tid = threadIdx.x;   // 128
    __shared__ int others[512];
    int lo = g_rowoff[n], cnt = g_rowoff[n+1] - lo;
    for (int q = tid; q < cnt; q += 128) {
        int v = g_rentry[lo + q];
        int e = v >> 1;
        others[q] = ((v & 1) ? ei[e] : ei[EE + e]) * FF;
    }
    __syncthreads();
    float a0 = 0.f, a1 = 0.f, a2 = 0.f, a3 = 0.f;
    int q = 0;
    for (; q + 4 <= cnt; q += 4) {
        a0 += g_m[others[q]   + tid];
        a1 += g_m[others[q+1] + tid];
        a2 += g_m[others[q+2] + tid];
        a3 += g_m[others[q+3] + tid];
    }
    for (; q < cnt; q++) a0 += g_m[others[q] + tid];
    g_nh[n*FF + tid] = g_base[n*FF + tid] + (a0 + a1 + a2 + a3) * 0.05f;
}

// ---------------- per-node outputs, 8 nodes per CTA ----------------
__global__ void __launch_bounds__(160) k_node_out(const float* __restrict__ Wem,
                                                  const float* __restrict__ Wproj,
                                                  const int* __restrict__ ntype) {
    int nb  = blockIdx.x * NODES8;
    int tid = threadIdx.x;             // 160
    __shared__ float nh[NODES8][FF];
    __shared__ int types[NODES8];
    for (int i = tid; i < NODES8*FF; i += 160) nh[i >> 7][i & 127] = g_nh[nb*FF + i];
    if (tid < NODES8) types[tid] = ntype[nb + tid];
    __syncthreads();
    int o = tid;
    if (o >= 139) return;
    const float4* w4 = 0; int stride4 = 0, kind, c0;
    if (o < 32)      { c0 = o*4;        w4 = (const float4*)(Wem + c0);             stride4 = HH/4; kind = 0; }
    else if (o < 64) { c0 = (o-32)*4;   w4 = (const float4*)(Wem + FF*HH + c0);     stride4 = HH/4; kind = 1; }
    else if (o < 80) { c0 = (o-64)*4;   w4 = (const float4*)(Wproj + FF*KK + c0);   stride4 = KK/4; kind = 2; }
    else if (o < 96) { c0 = (o-80)*4;   w4 = (const float4*)(Wproj + 2*FF*KK + c0); stride4 = KK/4; kind = 3; }
    else             { c0 = (o-96)*4;   kind = 4; }
    float4 acc[NODES8];
    #pragma unroll
    for (int m = 0; m < NODES8; m++) acc[m] = make_float4(0.f,0.f,0.f,0.f);
    if (kind < 4) {
        #pragma unroll 4
        for (int g = 0; g < FF; g++) {
            float4 w = w4[g*stride4];
            #pragma unroll
            for (int m = 0; m < NODES8; m++) {
                float h = nh[m][g];
                acc[m].x += h*w.x; acc[m].y += h*w.y; acc[m].z += h*w.z; acc[m].w += h*w.w;
            }
        }
    } else {
        const float4* wn[NODES8];
        #pragma unroll
        for (int m = 0; m < NODES8; m++) wn[m] = (const float4*)(g_Wn + types[m]*FF*WNS + c0);
        for (int g = 0; g < FF; g++) {
            #pragma unroll
            for (int m = 0; m < NODES8; m++) {
                float4 w = wn[m][g*(WNS/4)];
                float h = nh[m][g];
                acc[m].x += h*w.x; acc[m].y += h*w.y; acc[m].z += h*w.z; acc[m].w += h*w.w;
            }
        }
    }
    #pragma unroll
    for (int m = 0; m < NODES8; m++) {
        int n = nb + m;
        if (kind == 0)      *(float4*)&g_r1[n*HH + c0] = acc[m];
        else if (kind == 1) *(float4*)&g_r2[n*HH + c0] = acc[m];
        else if (kind == 2) *(float4*)&g_q1[n*KK + c0] = acc[m];
        else if (kind == 3) *(float4*)&g_q2[n*KK + c0] = acc[m];
        else {
            float v[4] = {acc[m].x, acc[m].y, acc[m].z, acc[m].w};
            #pragma unroll
            for (int j = 0; j < 4; j++) {
                int xy = c0 + j;
                if (xy < IEDGE) g_nblk[n*IEDGE + xy] = v[j];
            }
        }
    }
}

// ---------------- per-edge: edge_msg -> u -> h_ij/h_ji ----------------
__global__ void __launch_bounds__(128) k_edge_msg(const float* __restrict__ ef, const float* __restrict__ ea,
                                                  const float* __restrict__ Wem, const float* __restrict__ Wproj,
                                                  const int* __restrict__ ei) {
    __shared__ __align__(16) float wp[KK*WPPAD];
    __shared__ __align__(16) float msg[4][HH];
    __shared__ float eatt[4][32];
    __shared__ int sd[8];
    int tid = threadIdx.x;   // 128
    float emreg[32];
    #pragma unroll
    for (int j = 0; j < 32; j++) emreg[j] = Wem[(2*FF + j)*HH + tid];
    for (int i = tid; i < FF*KK; i += 128) {
        int r = i >> 6, c = i & 63;
        wp[c*WPPAD + r] = Wproj[i];
    }
    __syncthreads();
    for (int grp = blockIdx.x; grp < EE/4; grp += gridDim.x) {
        int e0 = grp*4;
        {
            int el = tid >> 5, j = tid & 31;
            eatt[el][j] = (j < EAD) ? ef[(e0+el)*EAD + j] : ea[(e0+el)*EAD + (j - EAD)];
        }
        if (tid < 8) sd[tid] = ei[(tid & 1)*EE + e0 + (tid >> 1)];
        __syncthreads();
        #pragma unroll
        for (int el = 0; el < 4; el++) {
            float fe = 0.f;
            #pragma unroll
            for (int j = 0; j < 32; j++) fe += eatt[el][j]*emreg[j];
            float pre = g_r1[sd[2*el]*HH + tid] + g_r2[sd[2*el+1]*HH + tid] + fe;
            float ex = __expf(2.f*pre);
            msg[el][tid] = 1.f - __fdividef(2.f, ex + 1.f);
        }
        __syncthreads();
        int c = tid & 63, hh = tid >> 6;
        const float4* wr = (const float4*)&wp[c*WPPAD];
        const float4* m0 = (const float4*)msg[2*hh];
        const float4* m1 = (const float4*)msg[2*hh + 1];
        float u0 = 0.f, u1 = 0.f;
        #pragma unroll 8
        for (int g = 0; g < HH/4; g++) {
            float4 w = wr[g]; float4 a = m0[g]; float4 b = m1[g];
            u0 += w.x*a.x + w.y*a.y + w.z*a.z + w.w*a.w;
            u1 += w.x*b.x + w.y*b.y + w.z*b.z + w.w*b.w;
        }
        #pragma unroll
        for (int q = 0; q < 2; q++) {
            int el = 2*hh + q;
            float u = q ? u1 : u0;
            int e = e0 + el, s = sd[2*el], d = sd[2*el + 1];
            g_h[e*2*KK + c]      = u + g_q1[s*KK + c] + g_q2[d*KK + c];
            g_h[e*2*KK + KK + c] = u + g_q1[d*KK + c] + g_q2[s*KK + c];
        }
        __syncthreads();
    }
}

// ---------------- per-edge 13x13 symmetrized blocks -> dense g_blk (no atomics) ----------------
__global__ void k_edge_blocks() {
    int p   = blockIdx.y;
    int tid = threadIdx.x;   // 192
    __shared__ __align__(16) float wc[IEDGE*WCPAD];
    __shared__ __align__(16) float hsm[4*2*KK];
    int beg = g_off[p], end = g_off[p+1];
    int cnt = end - beg;
    int per = (cnt + gridDim.x - 1) / gridDim.x;
    int lo  = beg + blockIdx.x * per;
    int hi  = min(lo + per, end);
    if (lo >= hi) return;
    const float* srcw = g_WcT + p*IEDGE*KK;
    for (int i = tid; i < IEDGE*(KK/4); i += blockDim.x) {
        int xy = i >> 4, kk = i & 15;
        ((float4*)(wc + xy*WCPAD))[kk] = ((const float4*)(srcw + xy*KK))[kk];
    }
    __syncthreads();
    int xyt = 0;
    if (tid < IEDGE) { int x = tid/DD; int y = tid - x*DD; xyt = y*DD + x; }
    for (int base = lo; base < hi; base += 4) {
        int ne = min(4, hi - base);
        for (int i = tid; i < 4*2*KK; i += blockDim.x) {
            int el = i >> 7, off = i & 127;
            float v = 0.f;
            if (el < ne) v = g_h[(size_t)g_bucket[base + el]*2*KK + off];
            hsm[i] = v;
        }
        __syncthreads();
        if (tid < IEDGE) {
            const float4* wf = (const float4*)(wc + tid*WCPAD);
            const float4* wt = (const float4*)(wc + xyt*WCPAD);
            const float4* h4 = (const float4*)hsm;
            float a[4] = {0.f,0.f,0.f,0.f}, b[4] = {0.f,0.f,0.f,0.f};
            #pragma unroll
            for (int kk = 0; kk < KK/4; kk++) {
                float4 f = wf[kk], t = wt[kk];
                #pragma unroll
                for (int el = 0; el < 4; el++) {
                    float4 hf = h4[el*32 + kk];
                    float4 hb = h4[el*32 + 16 + kk];
                    a[el] += hf.x*f.x + hf.y*f.y + hf.z*f.z + hf.w*f.w;
                    b[el] += hb.x*t.x + hb.y*t.y + hb.z*t.z + hb.w*t.w;
                }
            }
            #pragma unroll
            for (int el = 0; el < 4; el++) {
                if (el < ne) {
                    int e = g_bucket[base + el];
                    g_blk[(size_t)e*IEDGE + tid] = 0.5f*(a[el] + b[el]);
                }
            }
        }
        __syncthreads();
    }
}

// ---------------- assemble: build 2-row strips in smem, single TMA write of M ----------------
__global__ void __launch_bounds__(256) k_assemble(const int* __restrict__ ei,
                                                  char* __restrict__ M) {
    extern __shared__ __align__(128) float sm[];   // 2*13000 floats
    __shared__ int se[MAXDEG];    // e*2|flag
    __shared__ int sj[MAXDEG];    // col node
    int b   = blockIdx.x;
    int n   = b / CHUNKS;
    int ch  = b - n*CHUNKS;
    int x0  = ch * 2;
    int nr  = (ch == CHUNKS-1) ? 1 : 2;
    int tid = threadIdx.x;   // 256
    // zero strip
    int tot4 = nr * (NDIM/4);
    float4 z = make_float4(0.f,0.f,0.f,0.f);
    for (int i = tid; i < tot4; i += 256) ((float4*)sm)[i] = z;
    // stage CSR entries
    int lo = g_rowoff[n];
    int nent = g_rowoff[n+1] - lo;
    int nst = min(nent, MAXDEG);
    for (int q = tid; q < nst; q += 256) {
        int v = g_rentry[lo + q];
        se[q] = v;
        int e = v >> 1;
        sj[q] = (v & 1) ? ei[e] : ei[EE + e];
    }
    __syncthreads();
    // scatter edge blocks into smem (atomics: handles self-loops/dup edges)
    int NRC = nr * DD;
    int tot = nent * NRC;
    for (int w = tid; w < tot; w += 256) {
        int q  = w / NRC;
        int rc = w - q*NRC;
        int r  = rc / DD;
        int c  = rc - r*DD;
        int v, j;
        if (q < MAXDEG) { v = se[q]; j = sj[q]; }
        else { v = g_rentry[lo + q]; int e2 = v >> 1; j = (v & 1) ? ei[e2] : ei[EE + e2]; }
        int e = v >> 1;
        int idx = (v & 1) ? (c*DD + x0 + r) : ((x0 + r)*DD + c);
        float val = g_blk[(size_t)e*IEDGE + idx];
        atomicAdd(&sm[r*NDIM + j*DD + c], val);
    }
    // diagonal node block
    for (int rc = tid; rc < NRC; rc += 256) {
        int r = rc / DD, c = rc - (rc/DD)*DD;
        atomicAdd(&sm[r*NDIM + n*DD + c], g_nblk[n*IEDGE + (x0 + r)*DD + c]);
    }
    __syncthreads();
    asm volatile("fence.proxy.async.shared::cta;" ::: "memory");
    if (tid == 0) {
        uint32_t saddr;
        asm("{ .reg .u64 t; cvta.to.shared.u64 t, %1; cvt.u32.u64 %0, t; }" : "=r"(saddr) : "l"(sm));
        for (int r = 0; r < nr; r++) {
            char* dst = M + (size_t)(n*DD + x0 + r) * (NDIM*4);
            uint32_t src = saddr + r * (NDIM*4);
            // row = 52000 bytes: two bulk stores (32000 + 20000), both 16B-multiples
            asm volatile("cp.async.bulk.global.shared::cta.bulk_group [%0], [%1], %2;"
                         :: "l"(dst), "r"(src), "r"(32000u) : "memory");
            asm volatile("cp.async.bulk.global.shared::cta.bulk_group [%0], [%1], %2;"
                         :: "l"(dst + 32000), "r"(src + 32000u), "r"(20000u) : "memory");
        }
        asm volatile("cp.async.bulk.commit_group;" ::: "memory");
        asm volatile("cp.async.bulk.wait_group 0;" ::: "memory");
    }
    __syncthreads();
}

// ---------------- launcher ----------------
extern "C" void kernel_launch(void* const* d_in, const int* in_sizes, int n_in,
                              void* d_out, int out_size) {
    const float* nf    = (const float*)d_in[0];
    const float* na    = (const float*)d_in[1];
    const float* ef    = (const float*)d_in[2];
    const float* ea    = (const float*)d_in[3];
    const int*   ei    = (const int*)d_in[4];
    const int*   ntype = (const int*)d_in[5];
    const int*   etype = (const int*)d_in[6];
    const float* Wmsg  = (const float*)d_in[7];
    const float* Wattr = (const float*)d_in[8];
    const float* Wem   = (const float*)d_in[9];
    const float* Wproj = (const float*)d_in[10];
    const float* Wnode = (const float*)d_in[11];
    const float* Wedge = (const float*)d_in[12];
    const float* cobn  = (const float*)d_in[13];
    const float* cobe  = (const float*)d_in[14];
    float* M = (float*)d_out;

    static cudaStream_t s2 = 0;
    static cudaEvent_t evF = 0, evW = 0;
    if (!s2) {   // first call = non-captured correctness run: safe init point
        cudaStreamCreateWithFlags(&s2, cudaStreamNonBlocking);
        cudaEventCreateWithFlags(&evF, cudaEventDisableTiming);
        cudaEventCreateWithFlags(&evW, cudaEventDisableTiming);
        cudaFuncSetAttribute(k_assemble, cudaFuncAttributeMaxDynamicSharedMemorySize, ASM_SMEM);
    }

    // side branch: fused change-of-basis weights overlap the chain head
    cudaEventRecord(evF, 0);
    cudaStreamWaitEvent(s2, evF, 0);
    k_pre_node<<<32, 192, 0, s2>>>(Wnode, cobn);
    k_pre_edge<<<40, 192, 0, s2>>>(Wedge, cobe);
    cudaEventRecord(evW, s2);

    // main chain
    k_node_prep<<<NN, FF>>>(nf, na, Wmsg, Wattr);
    k_index<<<1, 1024>>>(ei, etype);
    k_gather<<<NN, 128>>>(ei);
    cudaStreamWaitEvent(0, evW, 0);
    k_node_out<<<NN/NODES8, 160>>>(Wem, Wproj, ntype);
    k_edge_msg<<<1480, 128>>>(ef, ea, Wem, Wproj, ei);
    k_edge_blocks<<<dim3(64, PP), 192>>>();
    k_assemble<<<NN*CHUNKS, 256, ASM_SMEM>>>(ei, (char*)M);
}

// round 9
// speedup vs baseline: 1.0953x; 1.0953x over previous
#include <cuda_runtime.h>
#include <math.h>
#include <stdint.h>

#define NN 1000
#define FF 128
#define TT 4
#define PP 10
#define DD 13
#define EE 20000
#define EAD 16
#define HH 128
#define KK 64
#define NDIM 13000        // N*D
#define IEDGE 169
#define INODE 91
#define WNS 172           // padded Wn row stride (mult of 4)
#define WCPAD 68          // padded Wc smem row stride
#define WPPAD 132         // padded Wp smem row stride
#define NODES8 8

// ---------------- scratch (device globals; no runtime allocation) ----------------
__device__ __align__(16) float g_m[NN*FF];
__device__ float g_base[NN*FF];
__device__ float g_nh[NN*FF];
__device__ float g_r1[NN*HH];
__device__ float g_r2[NN*HH];
__device__ float g_q1[NN*KK];
__device__ float g_q2[NN*KK];
__device__ __align__(16) float g_Wn[TT*FF*WNS];
__device__ __align__(16) float g_WcT[PP*IEDGE*KK];
__device__ __align__(16) float g_h[EE*2*KK];        // per-edge [h_ij(64) | h_ji(64)]
__device__ float g_nblk[NN*IEDGE];                  // node diagonal blocks
__device__ int   g_cnt[PP];
__device__ int   g_off[PP+1];
__device__ int   g_cur[PP];
__device__ int   g_rowcnt[NN];
__device__ int   g_rowoff[NN+1];
__device__ int   g_rowcur[NN];
__device__ int   g_bucket[EE];
__device__ int   g_rentry[2*EE];                    // e*2 | flag (flag=1 -> neighbor is src)

// ---------------- index pipeline (side stream): zero counters, hist, scan, bucket ----------------
__global__ void k_zero_cnt() {
    int t = threadIdx.x;   // 1024
    if (t < NN) { g_rowcnt[t] = 0; g_rowcur[t] = 0; }
    if (t < PP) { g_cnt[t] = 0; g_cur[t] = 0; }
}

__global__ void k_hist(const int* __restrict__ ei, const int* __restrict__ et) {
    int e = blockIdx.x*blockDim.x + threadIdx.x;
    if (e >= EE) return;
    atomicAdd(&g_cnt[et[e]], 1);
    atomicAdd(&g_rowcnt[ei[e]], 1);
    atomicAdd(&g_rowcnt[ei[EE + e]], 1);
}

__global__ void __launch_bounds__(1024) k_scan() {
    __shared__ int sm[1024];
    int tid = threadIdx.x;
    int v = (tid < NN) ? g_rowcnt[tid] : 0;
    sm[tid] = v;
    __syncthreads();
    #pragma unroll
    for (int off = 1; off < 1024; off <<= 1) {
        int t = (tid >= off) ? sm[tid - off] : 0;
        __syncthreads();
        sm[tid] += t;
        __syncthreads();
    }
    if (tid < NN) g_rowoff[tid] = sm[tid] - v;
    if (tid == NN - 1) g_rowoff[NN] = sm[tid];
    if (tid == 0) {
        int a = 0;
        for (int p = 0; p < PP; p++) { g_off[p] = a; a += g_cnt[p]; }
        g_off[PP] = a;
    }
}

__global__ void k_bucket(const int* __restrict__ ei, const int* __restrict__ et) {
    int e = blockIdx.x*blockDim.x + threadIdx.x;
    if (e >= EE) return;
    int p = et[e];
    g_bucket[g_off[p] + atomicAdd(&g_cur[p], 1)] = e;
    int s = ei[e], d = ei[EE + e];
    g_rentry[g_rowoff[s] + atomicAdd(&g_rowcur[s], 1)] = e*2;       // row s, neighbor = dst
    g_rentry[g_rowoff[d] + atomicAdd(&g_rowcur[d], 1)] = e*2 + 1;   // row d, neighbor = src
}

// ---------------- fused change-of-basis weights, coalesced tiled form ----------------
__global__ void __launch_bounds__(192) k_pre_node(const float* __restrict__ Wnode,
                                                  const float* __restrict__ cobn) {
    int t  = blockIdx.x & 3;
    int f0 = (blockIdx.x >> 2) * 16;
    int tid = threadIdx.x;   // 192
    __shared__ float Ws[INODE][17];
    for (int j = tid; j < 16*INODE; j += 192) {
        int f = j / INODE, i = j % INODE;
        Ws[i][f] = Wnode[(t*FF + f0 + f)*INODE + i];
    }
    for (int j = tid; j < 16*3; j += 192)
        g_Wn[(t*FF + f0 + j/3)*WNS + IEDGE + (j % 3)] = 0.f;
    __syncthreads();
    if (tid >= IEDGE) return;
    float acc[16];
    #pragma unroll
    for (int f = 0; f < 16; f++) acc[f] = 0.f;
    for (int i = 0; i < INODE; i++) {
        float cv = cobn[(t*INODE + i)*IEDGE + tid];
        #pragma unroll
        for (int f = 0; f < 16; f++) acc[f] += cv * Ws[i][f];
    }
    #pragma unroll
    for (int f = 0; f < 16; f++) g_Wn[(t*FF + f0 + f)*WNS + tid] = acc[f];
}

__global__ void __launch_bounds__(192) k_pre_edge(const float* __restrict__ Wedge,
                                                  const float* __restrict__ cobe) {
    int p  = blockIdx.x >> 2;
    int k0 = (blockIdx.x & 3) * 16;
    int tid = threadIdx.x;   // 192
    __shared__ float Ws[IEDGE][17];
    for (int j = tid; j < 16*IEDGE; j += 192) {
        int k = j / IEDGE, i = j % IEDGE;
        Ws[i][k] = Wedge[(p*KK + k0 + k)*IEDGE + i];
    }
    __syncthreads();
    if (tid >= IEDGE) return;
    float acc[16];
    #pragma unroll
    for (int k = 0; k < 16; k++) acc[k] = 0.f;
    for (int i = 0; i < IEDGE; i++) {
        float cv = cobe[((size_t)p*IEDGE + i)*IEDGE + tid];
        #pragma unroll
        for (int k = 0; k < 16; k++) acc[k] += cv * Ws[i][k];
    }
    float4* dst = (float4*)&g_WcT[(p*IEDGE + tid)*KK + k0];
    #pragma unroll
    for (int k4 = 0; k4 < 4; k4++)
        dst[k4] = make_float4(acc[4*k4], acc[4*k4+1], acc[4*k4+2], acc[4*k4+3]);
}

// ---------------- node prep: m = nf@Wmsg, base = nf + na@Wattr ----------------
__global__ void k_node_prep(const float* __restrict__ nf, const float* __restrict__ na,
                            const float* __restrict__ Wmsg, const float* __restrict__ Wattr) {
    int n = blockIdx.x;
    int f = threadIdx.x;   // 128
    int gt = n*FF + f;
    __shared__ float row[FF];
    row[f] = nf[gt];
    __syncthreads();
    float a0 = 0.f, a1 = 0.f, a2 = 0.f, a3 = 0.f;
    #pragma unroll 4
    for (int g = 0; g < FF; g += 4) {
        a0 += row[g]   * Wmsg[(g)*FF + f];
        a1 += row[g+1] * Wmsg[(g+1)*FF + f];
        a2 += row[g+2] * Wmsg[(g+2)*FF + f];
        a3 += row[g+3] * Wmsg[(g+3)*FF + f];
    }
    g_m[gt] = (a0 + a1) + (a2 + a3);
    float b = row[f];
    #pragma unroll
    for (int t = 0; t < TT; t++) b += na[n*TT + t] * Wattr[t*FF + f];
    g_base[gt] = b;
}

// ---------------- gather aggregation, chain-free ----------------
__global__ void __launch_bounds__(128) k_gather(const int* __restrict__ ei) {
    int n = blockIdx.x;
    int tid = threadIdx.x;   // 128
    __shared__ int others[512];
    int lo = g_rowoff[n], cnt = g_rowoff[n+1] - lo;
    for (int q = tid; q < cnt; q += 128) {
        int v = g_rentry[lo + q];
        int e = v >> 1;
        others[q] = ((v & 1) ? ei[e] : ei[EE + e]) * FF;
    }
    __syncthreads();
    float a0 = 0.f, a1 = 0.f, a2 = 0.f, a3 = 0.f;
    int q = 0;
    for (; q + 4 <= cnt; q += 4) {
        a0 += g_m[others[q]   + tid];
        a1 += g_m[others[q+1] + tid];
        a2 += g_m[others[q+2] + tid];
        a3 += g_m[others[q+3] + tid];
    }
    for (; q < cnt; q++) a0 += g_m[others[q] + tid];
    g_nh[n*FF + tid] = g_base[n*FF + tid] + (a0 + a1 + a2 + a3) * 0.05f;
}

// ---------------- per-node outputs, 8 nodes per CTA ----------------
__global__ void __launch_bounds__(160) k_node_out(const float* __restrict__ Wem,
                                                  const float* __restrict__ Wproj,
                                                  const int* __restrict__ ntype) {
    int nb  = blockIdx.x * NODES8;
    int tid = threadIdx.x;             // 160
    __shared__ float nh[NODES8][FF];
    __shared__ int types[NODES8];
    for (int i = tid; i < NODES8*FF; i += 160) nh[i >> 7][i & 127] = g_nh[nb*FF + i];
    if (tid < NODES8) types[tid] = ntype[nb + tid];
    __syncthreads();
    int o = tid;
    if (o >= 139) return;
    const float4* w4 = 0; int stride4 = 0, kind, c0;
    if (o < 32)      { c0 = o*4;        w4 = (const float4*)(Wem + c0);             stride4 = HH/4; kind = 0; }
    else if (o < 64) { c0 = (o-32)*4;   w4 = (const float4*)(Wem + FF*HH + c0);     stride4 = HH/4; kind = 1; }
    else if (o < 80) { c0 = (o-64)*4;   w4 = (const float4*)(Wproj + FF*KK + c0);   stride4 = KK/4; kind = 2; }
    else if (o < 96) { c0 = (o-80)*4;   w4 = (const float4*)(Wproj + 2*FF*KK + c0); stride4 = KK/4; kind = 3; }
    else             { c0 = (o-96)*4;   kind = 4; }
    float4 acc[NODES8];
    #pragma unroll
    for (int m = 0; m < NODES8; m++) acc[m] = make_float4(0.f,0.f,0.f,0.f);
    if (kind < 4) {
        #pragma unroll 4
        for (int g = 0; g < FF; g++) {
            float4 w = w4[g*stride4];
            #pragma unroll
            for (int m = 0; m < NODES8; m++) {
                float h = nh[m][g];
                acc[m].x += h*w.x; acc[m].y += h*w.y; acc[m].z += h*w.z; acc[m].w += h*w.w;
            }
        }
    } else {
        const float4* wn[NODES8];
        #pragma unroll
        for (int m = 0; m < NODES8; m++) wn[m] = (const float4*)(g_Wn + types[m]*FF*WNS + c0);
        for (int g = 0; g < FF; g++) {
            #pragma unroll
            for (int m = 0; m < NODES8; m++) {
                float4 w = wn[m][g*(WNS/4)];
                float h = nh[m][g];
                acc[m].x += h*w.x; acc[m].y += h*w.y; acc[m].z += h*w.z; acc[m].w += h*w.w;
            }
        }
    }
    #pragma unroll
    for (int m = 0; m < NODES8; m++) {
        int n = nb + m;
        if (kind == 0)      *(float4*)&g_r1[n*HH + c0] = acc[m];
        else if (kind == 1) *(float4*)&g_r2[n*HH + c0] = acc[m];
        else if (kind == 2) *(float4*)&g_q1[n*KK + c0] = acc[m];
        else if (kind == 3) *(float4*)&g_q2[n*KK + c0] = acc[m];
        else {
            float v[4] = {acc[m].x, acc[m].y, acc[m].z, acc[m].w};
            #pragma unroll
            for (int j = 0; j < 4; j++) {
                int xy = c0 + j;
                if (xy < IEDGE) g_nblk[n*IEDGE + xy] = v[j];
            }
        }
    }
}

// ---------------- per-edge: edge_msg -> u -> h_ij/h_ji ----------------
__global__ void __launch_bounds__(128) k_edge_msg(const float* __restrict__ ef, const float* __restrict__ ea,
                                                  const float* __restrict__ Wem, const float* __restrict__ Wproj,
                                                  const int* __restrict__ ei) {
    __shared__ __align__(16) float wp[KK*WPPAD];
    __shared__ __align__(16) float msg[4][HH];
    __shared__ float eatt[4][32];
    __shared__ int sd[8];
    int tid = threadIdx.x;   // 128
    float emreg[32];
    #pragma unroll
    for (int j = 0; j < 32; j++) emreg[j] = Wem[(2*FF + j)*HH + tid];
    for (int i = tid; i < FF*KK; i += 128) {
        int r = i >> 6, c = i & 63;
        wp[c*WPPAD + r] = Wproj[i];
    }
    __syncthreads();
    for (int grp = blockIdx.x; grp < EE/4; grp += gridDim.x) {
        int e0 = grp*4;
        {
            int el = tid >> 5, j = tid & 31;
            eatt[el][j] = (j < EAD) ? ef[(e0+el)*EAD + j] : ea[(e0+el)*EAD + (j - EAD)];
        }
        if (tid < 8) sd[tid] = ei[(tid & 1)*EE + e0 + (tid >> 1)];
        __syncthreads();
        #pragma unroll
        for (int el = 0; el < 4; el++) {
            float fe = 0.f;
            #pragma unroll
            for (int j = 0; j < 32; j++) fe += eatt[el][j]*emreg[j];
            float pre = g_r1[sd[2*el]*HH + tid] + g_r2[sd[2*el+1]*HH + tid] + fe;
            float ex = __expf(2.f*pre);
            msg[el][tid] = 1.f - __fdividef(2.f, ex + 1.f);
        }
        __syncthreads();
        int c = tid & 63, hh = tid >> 6;
        const float4* wr = (const float4*)&wp[c*WPPAD];
        const float4* m0 = (const float4*)msg[2*hh];
        const float4* m1 = (const float4*)msg[2*hh + 1];
        float u0 = 0.f, u1 = 0.f;
        #pragma unroll 8
        for (int g = 0; g < HH/4; g++) {
            float4 w = wr[g]; float4 a = m0[g]; float4 b = m1[g];
            u0 += w.x*a.x + w.y*a.y + w.z*a.z + w.w*a.w;
            u1 += w.x*b.x + w.y*b.y + w.z*b.z + w.w*b.w;
        }
        #pragma unroll
        for (int q = 0; q < 2; q++) {
            int el = 2*hh + q;
            float u = q ? u1 : u0;
            int e = e0 + el, s = sd[2*el], d = sd[2*el + 1];
            g_h[e*2*KK + c]      = u + g_q1[s*KK + c] + g_q2[d*KK + c];
            g_h[e*2*KK + KK + c] = u + g_q1[d*KK + c] + g_q2[s*KK + c];
        }
        __syncthreads();
    }
}

// ---------------- per-edge 13x13 blocks -> atomic scatter into zeroed M (+ diag blocks) ----------------
__global__ void k_edge_blocks(const int* __restrict__ ei, float* __restrict__ M) {
    int p   = blockIdx.y;
    int tid = threadIdx.x;   // 192
    if (p == PP) {           // diagonal node blocks
        int n0 = blockIdx.x * 16;
        int n1 = min(n0 + 16, NN);
        for (int n = n0; n < n1; n++)
            for (int j = tid; j < IEDGE; j += 192) {
                int x = j/DD, y = j - x*DD;
                atomicAdd(&M[(size_t)(n*DD + x)*NDIM + n*DD + y], g_nblk[n*IEDGE + j]);
            }
        return;
    }
    __shared__ __align__(16) float wc[IEDGE*WCPAD];
    __shared__ __align__(16) float hsm[4*2*KK];
    __shared__ int einfo[8];
    int beg = g_off[p], end = g_off[p+1];
    int cnt = end - beg;
    int per = (cnt + gridDim.x - 1) / gridDim.x;
    int lo  = beg + blockIdx.x * per;
    int hi  = min(lo + per, end);
    if (lo >= hi) return;
    const float* srcw = g_WcT + p*IEDGE*KK;
    for (int i = tid; i < IEDGE*(KK/4); i += blockDim.x) {
        int xy = i >> 4, kk = i & 15;
        ((float4*)(wc + xy*WCPAD))[kk] = ((const float4*)(srcw + xy*KK))[kk];
    }
    __syncthreads();
    int x = 0, y = 0, xyt = 0;
    if (tid < IEDGE) { x = tid/DD; y = tid - x*DD; xyt = y*DD + x; }
    for (int base = lo; base < hi; base += 4) {
        int ne = min(4, hi - base);
        for (int i = tid; i < 4*2*KK; i += blockDim.x) {
            int el = i >> 7, off = i & 127;
            float v = 0.f;
            if (el < ne) v = g_h[(size_t)g_bucket[base + el]*2*KK + off];
            hsm[i] = v;
        }
        if (tid < 8) {
            int el = tid >> 1;
            int e = g_bucket[base + min(el, ne - 1)];
            einfo[tid] = ei[(tid & 1)*EE + e];
        }
        __syncthreads();
        if (tid < IEDGE) {
            const float4* wf = (const float4*)(wc + tid*WCPAD);
            const float4* wt = (const float4*)(wc + xyt*WCPAD);
            const float4* h4 = (const float4*)hsm;
            float a[4] = {0.f,0.f,0.f,0.f}, b[4] = {0.f,0.f,0.f,0.f};
            #pragma unroll
            for (int kk = 0; kk < KK/4; kk++) {
                float4 f = wf[kk], t = wt[kk];
                #pragma unroll
                for (int el = 0; el < 4; el++) {
                    float4 hf = h4[el*32 + kk];
                    float4 hb = h4[el*32 + 16 + kk];
                    a[el] += hf.x*f.x + hf.y*f.y + hf.z*f.z + hf.w*f.w;
                    b[el] += hb.x*t.x + hb.y*t.y + hb.z*t.z + hb.w*t.w;
                }
            }
            #pragma unroll
            for (int el = 0; el < 4; el++) {
                if (el < ne) {
                    float v = 0.5f*(a[el] + b[el]);
                    int s = einfo[2*el], d = einfo[2*el + 1];
                    atomicAdd(&M[(size_t)(s*DD + x)*NDIM + d*DD + y], v);
                    atomicAdd(&M[(size_t)(d*DD + y)*NDIM + s*DD + x], v);
                }
            }
        }
        __syncthreads();
    }
}

// ---------------- launcher: fork-join graph; resources created once on call 1 ----------------
extern "C" void kernel_launch(void* const* d_in, const int* in_sizes, int n_in,
                              void* d_out, int out_size) {
    const float* nf    = (const float*)d_in[0];
    const float* na    = (const float*)d_in[1];
    const float* ef    = (const float*)d_in[2];
    const float* ea    = (const float*)d_in[3];
    const int*   ei    = (const int*)d_in[4];
    const int*   ntype = (const int*)d_in[5];
    const int*   etype = (const int*)d_in[6];
    const float* Wmsg  = (const float*)d_in[7];
    const float* Wattr = (const float*)d_in[8];
    const float* Wem   = (const float*)d_in[9];
    const float* Wproj = (const float*)d_in[10];
    const float* Wnode = (const float*)d_in[11];
    const float* Wedge = (const float*)d_in[12];
    const float* cobn  = (const float*)d_in[13];
    const float* cobe  = (const float*)d_in[14];
    float* M = (float*)d_out;

    static cudaStream_t s1 = 0, s2 = 0;
    static cudaEvent_t evF = 0, evZ = 0, evB = 0, evW = 0;
    if (!s1) {   // first call = non-captured correctness run: safe init point
        cudaStreamCreateWithFlags(&s1, cudaStreamNonBlocking);
        cudaStreamCreateWithFlags(&s2, cudaStreamNonBlocking);
        cudaEventCreateWithFlags(&evF, cudaEventDisableTiming);
        cudaEventCreateWithFlags(&evZ, cudaEventDisableTiming);
        cudaEventCreateWithFlags(&evB, cudaEventDisableTiming);
        cudaEventCreateWithFlags(&evW, cudaEventDisableTiming);
    }

    // fork
    cudaEventRecord(evF, 0);
    cudaStreamWaitEvent(s1, evF, 0);
    cudaStreamWaitEvent(s2, evF, 0);

    // branch 1: zero the 676MB output (driver memset node, overlaps the whole chain)
    cudaMemsetAsync(M, 0, (size_t)out_size * sizeof(float), s1);
    cudaEventRecord(evZ, s1);

    // branch 2: index pipeline, then fused change-of-basis weights
    k_zero_cnt<<<1, 1024, 0, s2>>>();
    k_hist<<<(EE + 255)/256, 256, 0, s2>>>(ei, etype);
    k_scan<<<1, 1024, 0, s2>>>();
    k_bucket<<<(EE + 255)/256, 256, 0, s2>>>(ei, etype);
    cudaEventRecord(evB, s2);
    k_pre_node<<<32, 192, 0, s2>>>(Wnode, cobn);
    k_pre_edge<<<40, 192, 0, s2>>>(Wedge, cobe);
    cudaEventRecord(evW, s2);

    // main chain
    k_node_prep<<<NN, FF>>>(nf, na, Wmsg, Wattr);
    cudaStreamWaitEvent(0, evB, 0);
    k_gather<<<NN, 128>>>(ei);
    cudaStreamWaitEvent(0, evW, 0);
    k_node_out<<<NN/NODES8, 160>>>(Wem, Wproj, ntype);
    k_edge_msg<<<1480, 128>>>(ef, ea, Wem, Wproj, ei);
    cudaStreamWaitEvent(0, evZ, 0);
    k_edge_blocks<<<dim3(64, PP+1), 192>>>(ei, M);
}

// round 10
// speedup vs baseline: 1.1724x; 1.0704x over previous
#include <cuda_runtime.h>
#include <math.h>
#include <stdint.h>

#define NN 1000
#define FF 128
#define TT 4
#define PP 10
#define DD 13
#define EE 20000
#define EAD 16
#define HH 128
#define KK 64
#define NDIM 13000        // N*D
#define IEDGE 169
#define INODE 91
#define WNS 172           // padded Wn row stride (mult of 4)
#define WCPAD 68          // padded Wc smem row stride
#define WPPAD 132         // padded Wp smem row stride
#define NODES8 8

#define ZCH  32768u       // TMA chunk
#define NFULL 20629u      // full chunks
#define TAILB 28928u      // remainder bytes (676e6 - 20629*32768), mult of 16

// ---------------- scratch (device globals; no runtime allocation) ----------------
__device__ __align__(16) float g_m[NN*FF];
__device__ float g_base[NN*FF];
__device__ float g_nh[NN*FF];
__device__ float g_r1[NN*HH];
__device__ float g_r2[NN*HH];
__device__ float g_q1[NN*KK];
__device__ float g_q2[NN*KK];
__device__ __align__(16) float g_Wn[TT*FF*WNS];
__device__ __align__(16) float g_WcT[PP*IEDGE*KK];
__device__ __align__(16) float g_h[EE*2*KK];        // per-edge [h_ij(64) | h_ji(64)]
__device__ float g_nblk[NN*IEDGE];                  // node diagonal blocks
__device__ int   g_cnt[PP];
__device__ int   g_off[PP+1];
__device__ int   g_cur[PP];
__device__ int   g_rowcnt[NN];
__device__ int   g_rowoff[NN+1];
__device__ int   g_rowcur[NN];
__device__ int   g_bucket[EE];
__device__ int   g_rentry[2*EE];                    // e*2 | flag (flag=1 -> neighbor is src)

// ---------------- zero M via TMA bulk stores (issue-light, leaves SMs free) ----------------
__global__ void __launch_bounds__(256) k_zero_tma(char* __restrict__ M) {
    __shared__ __align__(128) float4 zbuf[ZCH/16];   // 32KB of zeros
    int tid = threadIdx.x;
    float4 z = make_float4(0.f, 0.f, 0.f, 0.f);
    #pragma unroll
    for (int i = 0; i < (int)(ZCH/16/256); i++) zbuf[tid + i*256] = z;
    __syncthreads();
    if (tid != 0) return;
    asm volatile("fence.proxy.async.shared::cta;" ::: "memory");
    uint32_t saddr;
    asm("{ .reg .u64 t; cvta.to.shared.u64 t, %1; cvt.u32.u64 %0, t; }" : "=r"(saddr) : "l"(zbuf));
    for (uint32_t c = blockIdx.x; c < NFULL + 1; c += gridDim.x) {
        char* dst = M + (size_t)c * ZCH;
        uint32_t bytes = (c == NFULL) ? TAILB : ZCH;
        asm volatile("cp.async.bulk.global.shared::cta.bulk_group [%0], [%1], %2;"
                     :: "l"(dst), "r"(saddr), "r"(bytes) : "memory");
    }
    asm volatile("cp.async.bulk.commit_group;" ::: "memory");
    asm volatile("cp.async.bulk.wait_group 0;" ::: "memory");
}

// ---------------- index pipeline (side stream) ----------------
__global__ void k_zero_cnt() {
    int t = threadIdx.x;   // 1024
    if (t < NN) { g_rowcnt[t] = 0; g_rowcur[t] = 0; }
    if (t < PP) { g_cnt[t] = 0; g_cur[t] = 0; }
}

__global__ void k_hist(const int* __restrict__ ei, const int* __restrict__ et) {
    int e = blockIdx.x*blockDim.x + threadIdx.x;
    if (e >= EE) return;
    atomicAdd(&g_cnt[et[e]], 1);
    atomicAdd(&g_rowcnt[ei[e]], 1);
    atomicAdd(&g_rowcnt[ei[EE + e]], 1);
}

__global__ void __launch_bounds__(1024) k_scan() {
    __shared__ int sm[1024];
    int tid = threadIdx.x;
    int v = (tid < NN) ? g_rowcnt[tid] : 0;
    sm[tid] = v;
    __syncthreads();
    #pragma unroll
    for (int off = 1; off < 1024; off <<= 1) {
        int t = (tid >= off) ? sm[tid - off] : 0;
        __syncthreads();
        sm[tid] += t;
        __syncthreads();
    }
    if (tid < NN) g_rowoff[tid] = sm[tid] - v;
    if (tid == NN - 1) g_rowoff[NN] = sm[tid];
    if (tid == 0) {
        int a = 0;
        for (int p = 0; p < PP; p++) { g_off[p] = a; a += g_cnt[p]; }
        g_off[PP] = a;
    }
}

__global__ void k_bucket(const int* __restrict__ ei, const int* __restrict__ et) {
    int e = blockIdx.x*blockDim.x + threadIdx.x;
    if (e >= EE) return;
    int p = et[e];
    g_bucket[g_off[p] + atomicAdd(&g_cur[p], 1)] = e;
    int s = ei[e], d = ei[EE + e];
    g_rentry[g_rowoff[s] + atomicAdd(&g_rowcur[s], 1)] = e*2;       // row s, neighbor = dst
    g_rentry[g_rowoff[d] + atomicAdd(&g_rowcur[d], 1)] = e*2 + 1;   // row d, neighbor = src
}

// ---------------- fused change-of-basis weights, coalesced tiled form ----------------
__global__ void __launch_bounds__(192) k_pre_node(const float* __restrict__ Wnode,
                                                  const float* __restrict__ cobn) {
    int t  = blockIdx.x & 3;
    int f0 = (blockIdx.x >> 2) * 16;
    int tid = threadIdx.x;   // 192
    __shared__ float Ws[INODE][17];
    for (int j = tid; j < 16*INODE; j += 192) {
        int f = j / INODE, i = j % INODE;
        Ws[i][f] = Wnode[(t*FF + f0 + f)*INODE + i];
    }
    for (int j = tid; j < 16*3; j += 192)
        g_Wn[(t*FF + f0 + j/3)*WNS + IEDGE + (j % 3)] = 0.f;
    __syncthreads();
    if (tid >= IEDGE) return;
    float acc[16];
    #pragma unroll
    for (int f = 0; f < 16; f++) acc[f] = 0.f;
    for (int i = 0; i < INODE; i++) {
        float cv = cobn[(t*INODE + i)*IEDGE + tid];
        #pragma unroll
        for (int f = 0; f < 16; f++) acc[f] += cv * Ws[i][f];
    }
    #pragma unroll
    for (int f = 0; f < 16; f++) g_Wn[(t*FF + f0 + f)*WNS + tid] = acc[f];
}

__global__ void __launch_bounds__(192) k_pre_edge(const float* __restrict__ Wedge,
                                                  const float* __restrict__ cobe) {
    int p  = blockIdx.x >> 2;
    int k0 = (blockIdx.x & 3) * 16;
    int tid = threadIdx.x;   // 192
    __shared__ float Ws[IEDGE][17];
    for (int j = tid; j < 16*IEDGE; j += 192) {
        int k = j / IEDGE, i = j % IEDGE;
        Ws[i][k] = Wedge[(p*KK + k0 + k)*IEDGE + i];
    }
    __syncthreads();
    if (tid >= IEDGE) return;
    float acc[16];
    #pragma unroll
    for (int k = 0; k < 16; k++) acc[k] = 0.f;
    for (int i = 0; i < IEDGE; i++) {
        float cv = cobe[((size_t)p*IEDGE + i)*IEDGE + tid];
        #pragma unroll
        for (int k = 0; k < 16; k++) acc[k] += cv * Ws[i][k];
    }
    float4* dst = (float4*)&g_WcT[(p*IEDGE + tid)*KK + k0];
    #pragma unroll
    for (int k4 = 0; k4 < 4; k4++)
        dst[k4] = make_float4(acc[4*k4], acc[4*k4+1], acc[4*k4+2], acc[4*k4+3]);
}

// ---------------- node prep: m = nf@Wmsg, base = nf + na@Wattr ----------------
__global__ void k_node_prep(const float* __restrict__ nf, const float* __restrict__ na,
                            const float* __restrict__ Wmsg, const float* __restrict__ Wattr) {
    int n = blockIdx.x;
    int f = threadIdx.x;   // 128
    int gt = n*FF + f;
    __shared__ float row[FF];
    row[f] = nf[gt];
    __syncthreads();
    float a0 = 0.f, a1 = 0.f, a2 = 0.f, a3 = 0.f;
    #pragma unroll 4
    for (int g = 0; g < FF; g += 4) {
        a0 += row[g]   * Wmsg[(g)*FF + f];
        a1 += row[g+1] * Wmsg[(g+1)*FF + f];
        a2 += row[g+2] * Wmsg[(g+2)*FF + f];
        a3 += row[g+3] * Wmsg[(g+3)*FF + f];
    }
    g_m[gt] = (a0 + a1) + (a2 + a3);
    float b = row[f];
    #pragma unroll
    for (int t = 0; t < TT; t++) b += na[n*TT + t] * Wattr[t*FF + f];
    g_base[gt] = b;
}

// ---------------- gather aggregation, chain-free ----------------
__global__ void __launch_bounds__(128) k_gather(const int* __restrict__ ei) {
    int n = blockIdx.x;
    int tid = threadIdx.x;   // 128
    __shared__ int others[512];
    int lo = g_rowoff[n], cnt = g_rowoff[n+1] - lo;
    for (int q = tid; q < cnt; q += 128) {
        int v = g_rentry[lo + q];
        int e = v >> 1;
        others[q] = ((v & 1) ? ei[e] : ei[EE + e]) * FF;
    }
    __syncthreads();
    float a0 = 0.f, a1 = 0.f, a2 = 0.f, a3 = 0.f;
    int q = 0;
    for (; q + 4 <= cnt; q += 4) {
        a0 += g_m[others[q]   + tid];
        a1 += g_m[others[q+1] + tid];
        a2 += g_m[others[q+2] + tid];
        a3 += g_m[others[q+3] + tid];
    }
    for (; q < cnt; q++) a0 += g_m[others[q] + tid];
    g_nh[n*FF + tid] = g_base[n*FF + tid] + (a0 + a1 + a2 + a3) * 0.05f;
}

// ---------------- per-node outputs, 8 nodes per CTA ----------------
__global__ void __launch_bounds__(160) k_node_out(const float* __restrict__ Wem,
                                                  const float* __restrict__ Wproj,
                                                  const int* __restrict__ ntype) {
    int nb  = blockIdx.x * NODES8;
    int tid = threadIdx.x;             // 160
    __shared__ float nh[NODES8][FF];
    __shared__ int types[NODES8];
    for (int i = tid; i < NODES8*FF; i += 160) nh[i >> 7][i & 127] = g_nh[nb*FF + i];
    if (tid < NODES8) types[tid] = ntype[nb + tid];
    __syncthreads();
    int o = tid;
    if (o >= 139) return;
    const float4* w4 = 0; int stride4 = 0, kind, c0;
    if (o < 32)      { c0 = o*4;        w4 = (const float4*)(Wem + c0);             stride4 = HH/4; kind = 0; }
    else if (o < 64) { c0 = (o-32)*4;   w4 = (const float4*)(Wem + FF*HH + c0);     stride4 = HH/4; kind = 1; }
    else if (o < 80) { c0 = (o-64)*4;   w4 = (const float4*)(Wproj + FF*KK + c0);   stride4 = KK/4; kind = 2; }
    else if (o < 96) { c0 = (o-80)*4;   w4 = (const float4*)(Wproj + 2*FF*KK + c0); stride4 = KK/4; kind = 3; }
    else             { c0 = (o-96)*4;   kind = 4; }
    float4 acc[NODES8];
    #pragma unroll
    for (int m = 0; m < NODES8; m++) acc[m] = make_float4(0.f,0.f,0.f,0.f);
    if (kind < 4) {
        #pragma unroll 4
        for (int g = 0; g < FF; g++) {
            float4 w = w4[g*stride4];
            #pragma unroll
            for (int m = 0; m < NODES8; m++) {
                float h = nh[m][g];
                acc[m].x += h*w.x; acc[m].y += h*w.y; acc[m].z += h*w.z; acc[m].w += h*w.w;
            }
        }
    } else {
        const float4* wn[NODES8];
        #pragma unroll
        for (int m = 0; m < NODES8; m++) wn[m] = (const float4*)(g_Wn + types[m]*FF*WNS + c0);
        for (int g = 0; g < FF; g++) {
            #pragma unroll
            for (int m = 0; m < NODES8; m++) {
                float4 w = wn[m][g*(WNS/4)];
                float h = nh[m][g];
                acc[m].x += h*w.x; acc[m].y += h*w.y; acc[m].z += h*w.z; acc[m].w += h*w.w;
            }
        }
    }
    #pragma unroll
    for (int m = 0; m < NODES8; m++) {
        int n = nb + m;
        if (kind == 0)      *(float4*)&g_r1[n*HH + c0] = acc[m];
        else if (kind == 1) *(float4*)&g_r2[n*HH + c0] = acc[m];
        else if (kind == 2) *(float4*)&g_q1[n*KK + c0] = acc[m];
        else if (kind == 3) *(float4*)&g_q2[n*KK + c0] = acc[m];
        else {
            float v[4] = {acc[m].x, acc[m].y, acc[m].z, acc[m].w};
            #pragma unroll
            for (int j = 0; j < 4; j++) {
                int xy = c0 + j;
                if (xy < IEDGE) g_nblk[n*IEDGE + xy] = v[j];
            }
        }
    }
}

// ---------------- per-edge: edge_msg -> u -> h_ij/h_ji ----------------
__global__ void __launch_bounds__(128) k_edge_msg(const float* __restrict__ ef, const float* __restrict__ ea,
                                                  const float* __restrict__ Wem, const float* __restrict__ Wproj,
                                                  const int* __restrict__ ei) {
    __shared__ __align__(16) float wp[KK*WPPAD];
    __shared__ __align__(16) float msg[4][HH];
    __shared__ float eatt[4][32];
    __shared__ int sd[8];
    int tid = threadIdx.x;   // 128
    float emreg[32];
    #pragma unroll
    for (int j = 0; j < 32; j++) emreg[j] = Wem[(2*FF + j)*HH + tid];
    for (int i = tid; i < FF*KK; i += 128) {
        int r = i >> 6, c = i & 63;
        wp[c*WPPAD + r] = Wproj[i];
    }
    __syncthreads();
    for (int grp = blockIdx.x; grp < EE/4; grp += gridDim.x) {
        int e0 = grp*4;
        {
            int el = tid >> 5, j = tid & 31;
            eatt[el][j] = (j < EAD) ? ef[(e0+el)*EAD + j] : ea[(e0+el)*EAD + (j - EAD)];
        }
        if (tid < 8) sd[tid] = ei[(tid & 1)*EE + e0 + (tid >> 1)];
        __syncthreads();
        #pragma unroll
        for (int el = 0; el < 4; el++) {
            float fe = 0.f;
            #pragma unroll
            for (int j = 0; j < 32; j++) fe += eatt[el][j]*emreg[j];
            float pre = g_r1[sd[2*el]*HH + tid] + g_r2[sd[2*el+1]*HH + tid] + fe;
            float ex = __expf(2.f*pre);
            msg[el][tid] = 1.f - __fdividef(2.f, ex + 1.f);
        }
        __syncthreads();
        int c = tid & 63, hh = tid >> 6;
        const float4* wr = (const float4*)&wp[c*WPPAD];
        const float4* m0 = (const float4*)msg[2*hh];
        const float4* m1 = (const float4*)msg[2*hh + 1];
        float u0 = 0.f, u1 = 0.f;
        #pragma unroll 8
        for (int g = 0; g < HH/4; g++) {
            float4 w = wr[g]; float4 a = m0[g]; float4 b = m1[g];
            u0 += w.x*a.x + w.y*a.y + w.z*a.z + w.w*a.w;
            u1 += w.x*b.x + w.y*b.y + w.z*b.z + w.w*b.w;
        }
        #pragma unroll
        for (int q = 0; q < 2; q++) {
            int el = 2*hh + q;
            float u = q ? u1 : u0;
            int e = e0 + el, s = sd[2*el], d = sd[2*el + 1];
            g_h[e*2*KK + c]      = u + g_q1[s*KK + c] + g_q2[d*KK + c];
            g_h[e*2*KK + KK + c] = u + g_q1[d*KK + c] + g_q2[s*KK + c];
        }
        __syncthreads();
    }
}

// ---------------- per-edge 13x13 blocks -> atomic scatter into zeroed M (+ diag blocks) ----------------
__global__ void k_edge_blocks(const int* __restrict__ ei, float* __restrict__ M) {
    int p   = blockIdx.y;
    int tid = threadIdx.x;   // 192
    if (p == PP) {           // diagonal node blocks
        int n0 = blockIdx.x * 16;
        int n1 = min(n0 + 16, NN);
        for (int n = n0; n < n1; n++)
            for (int j = tid; j < IEDGE; j += 192) {
                int x = j/DD, y = j - x*DD;
                atomicAdd(&M[(size_t)(n*DD + x)*NDIM + n*DD + y], g_nblk[n*IEDGE + j]);
            }
        return;
    }
    __shared__ __align__(16) float wc[IEDGE*WCPAD];
    __shared__ __align__(16) float hsm[4*2*KK];
    __shared__ int einfo[8];
    int beg = g_off[p], end = g_off[p+1];
    int cnt = end - beg;
    int per = (cnt + gridDim.x - 1) / gridDim.x;
    int lo  = beg + blockIdx.x * per;
    int hi  = min(lo + per, end);
    if (lo >= hi) return;
    const float* srcw = g_WcT + p*IEDGE*KK;
    for (int i = tid; i < IEDGE*(KK/4); i += blockDim.x) {
        int xy = i >> 4, kk = i & 15;
        ((float4*)(wc + xy*WCPAD))[kk] = ((const float4*)(srcw + xy*KK))[kk];
    }
    __syncthreads();
    int x = 0, y = 0, xyt = 0;
    if (tid < IEDGE) { x = tid/DD; y = tid - x*DD; xyt = y*DD + x; }
    for (int base = lo; base < hi; base += 4) {
        int ne = min(4, hi - base);
        for (int i = tid; i < 4*2*KK; i += blockDim.x) {
            int el = i >> 7, off = i & 127;
            float v = 0.f;
            if (el < ne) v = g_h[(size_t)g_bucket[base + el]*2*KK + off];
            hsm[i] = v;
        }
        if (tid < 8) {
            int el = tid >> 1;
            int e = g_bucket[base + min(el, ne - 1)];
            einfo[tid] = ei[(tid & 1)*EE + e];
        }
        __syncthreads();
        if (tid < IEDGE) {
            const float4* wf = (const float4*)(wc + tid*WCPAD);
            const float4* wt = (const float4*)(wc + xyt*WCPAD);
            const float4* h4 = (const float4*)hsm;
            float a[4] = {0.f,0.f,0.f,0.f}, b[4] = {0.f,0.f,0.f,0.f};
            #pragma unroll
            for (int kk = 0; kk < KK/4; kk++) {
                float4 f = wf[kk], t = wt[kk];
                #pragma unroll
                for (int el = 0; el < 4; el++) {
                    float4 hf = h4[el*32 + kk];
                    float4 hb = h4[el*32 + 16 + kk];
                    a[el] += hf.x*f.x + hf.y*f.y + hf.z*f.z + hf.w*f.w;
                    b[el] += hb.x*t.x + hb.y*t.y + hb.z*t.z + hb.w*t.w;
                }
            }
            #pragma unroll
            for (int el = 0; el < 4; el++) {
                if (el < ne) {
                    float v = 0.5f*(a[el] + b[el]);
                    int s = einfo[2*el], d = einfo[2*el + 1];
                    atomicAdd(&M[(size_t)(s*DD + x)*NDIM + d*DD + y], v);
                    atomicAdd(&M[(size_t)(d*DD + y)*NDIM + s*DD + x], v);
                }
            }
        }
        __syncthreads();
    }
}

// ---------------- launcher: fork-join graph; resources created once on call 1 ----------------
extern "C" void kernel_launch(void* const* d_in, const int* in_sizes, int n_in,
                              void* d_out, int out_size) {
    const float* nf    = (const float*)d_in[0];
    const float* na    = (const float*)d_in[1];
    const float* ef    = (const float*)d_in[2];
    const float* ea    = (const float*)d_in[3];
    const int*   ei    = (const int*)d_in[4];
    const int*   ntype = (const int*)d_in[5];
    const int*   etype = (const int*)d_in[6];
    const float* Wmsg  = (const float*)d_in[7];
    const float* Wattr = (const float*)d_in[8];
    const float* Wem   = (const float*)d_in[9];
    const float* Wproj = (const float*)d_in[10];
    const float* Wnode = (const float*)d_in[11];
    const float* Wedge = (const float*)d_in[12];
    const float* cobn  = (const float*)d_in[13];
    const float* cobe  = (const float*)d_in[14];
    float* M = (float*)d_out;

    static cudaStream_t s1 = 0, s2 = 0;
    static cudaEvent_t evF = 0, evZ = 0, evB = 0, evW = 0;
    if (!s1) {   // first call = non-captured correctness run: safe init point
        cudaStreamCreateWithFlags(&s1, cudaStreamNonBlocking);
        cudaStreamCreateWithFlags(&s2, cudaStreamNonBlocking);
        cudaEventCreateWithFlags(&evF, cudaEventDisableTiming);
        cudaEventCreateWithFlags(&evZ, cudaEventDisableTiming);
        cudaEventCreateWithFlags(&evB, cudaEventDisableTiming);
        cudaEventCreateWithFlags(&evW, cudaEventDisableTiming);
    }

    // fork
    cudaEventRecord(evF, 0);
    cudaStreamWaitEvent(s1, evF, 0);
    cudaStreamWaitEvent(s2, evF, 0);

    // branch 1: zero 676MB via TMA bulk stores (issue-light; SMs stay free)
    k_zero_tma<<<148, 256, 0, s1>>>((char*)M);
    cudaEventRecord(evZ, s1);

    // branch 2: index pipeline, then fused change-of-basis weights
    k_zero_cnt<<<1, 1024, 0, s2>>>();
    k_hist<<<(EE + 255)/256, 256, 0, s2>>>(ei, etype);
    k_scan<<<1, 1024, 0, s2>>>();
    k_bucket<<<(EE + 255)/256, 256, 0, s2>>>(ei, etype);
    cudaEventRecord(evB, s2);
    k_pre_node<<<32, 192, 0, s2>>>(Wnode, cobn);
    k_pre_edge<<<40, 192, 0, s2>>>(Wedge, cobe);
    cudaEventRecord(evW, s2);

    // main chain
    k_node_prep<<<NN, FF>>>(nf, na, Wmsg, Wattr);
    cudaStreamWaitEvent(0, evB, 0);
    k_gather<<<NN, 128>>>(ei);
    cudaStreamWaitEvent(0, evW, 0);
    k_node_out<<<NN/NODES8, 160>>>(Wem, Wproj, ntype);
    k_edge_msg<<<1480, 128>>>(ef, ea, Wem, Wproj, ei);
    cudaStreamWaitEvent(0, evZ, 0);
    k_edge_blocks<<<dim3(64, PP+1), 192>>>(ei, M);
}

// round 11
// speedup vs baseline: 1.1731x; 1.0006x over previous
#include <cuda_runtime.h>
#include <math.h>
#include <stdint.h>

#define NN 1000
#define FF 128
#define TT 4
#define PP 10
#define DD 13
#define EE 20000
#define EAD 16
#define HH 128
#define KK 64
#define NDIM 13000        // N*D
#define IEDGE 169
#define INODE 91
#define WNS 172           // padded Wn row stride (mult of 4)
#define WCPAD 68          // padded Wc smem row stride
#define WPPAD 132         // padded Wp smem row stride
#define NODES8 8

#define ZCH  32768u       // TMA chunk
#define NFULL 20629u      // full chunks
#define TAILB 28928u      // remainder bytes (676e6 - 20629*32768), mult of 16

// ---------------- scratch (device globals; no runtime allocation) ----------------
__device__ __align__(16) float g_m[NN*FF];
__device__ float g_base[NN*FF];
__device__ float g_nh[NN*FF];
__device__ float g_r1[NN*HH];
__device__ float g_r2[NN*HH];
__device__ float g_q1[NN*KK];
__device__ float g_q2[NN*KK];
__device__ __align__(16) float g_Wn[TT*FF*WNS];
__device__ __align__(16) float g_WcT[PP*IEDGE*KK];
__device__ __align__(16) float g_h[EE*2*KK];        // per-edge [h_ij(64) | h_ji(64)]
__device__ float g_nblk[NN*IEDGE];                  // node diagonal blocks
__device__ int   g_cnt[PP];
__device__ int   g_off[PP+1];
__device__ int   g_cur[PP];
__device__ int   g_rowcnt[NN];
__device__ int   g_rowoff[NN+1];
__device__ int   g_rowcur[NN];
__device__ int   g_bucket[EE];
__device__ int   g_rentry[2*EE];                    // e*2 | flag (flag=1 -> neighbor is src)

// ---------------- zero M via TMA bulk stores; 3 CTAs/SM to saturate TMA service ----------------
__global__ void __launch_bounds__(256) k_zero_tma(char* __restrict__ M) {
    __shared__ __align__(128) float4 zbuf[ZCH/16];   // 32KB of zeros
    int tid = threadIdx.x;
    float4 z = make_float4(0.f, 0.f, 0.f, 0.f);
    #pragma unroll
    for (int i = 0; i < (int)(ZCH/16/256); i++) zbuf[tid + i*256] = z;
    __syncthreads();
    if (tid != 0) return;
    asm volatile("fence.proxy.async.shared::cta;" ::: "memory");
    uint32_t saddr;
    asm("{ .reg .u64 t; cvta.to.shared.u64 t, %1; cvt.u32.u64 %0, t; }" : "=r"(saddr) : "l"(zbuf));
    for (uint32_t c = blockIdx.x; c < NFULL + 1; c += gridDim.x) {
        char* dst = M + (size_t)c * ZCH;
        uint32_t bytes = (c == NFULL) ? TAILB : ZCH;
        asm volatile("cp.async.bulk.global.shared::cta.bulk_group [%0], [%1], %2;"
                     :: "l"(dst), "r"(saddr), "r"(bytes) : "memory");
    }
    asm volatile("cp.async.bulk.commit_group;" ::: "memory");
    asm volatile("cp.async.bulk.wait_group 0;" ::: "memory");
}

// ---------------- index pipeline (side stream) ----------------
__global__ void k_zero_cnt() {
    int t = threadIdx.x;   // 1024
    if (t < NN) { g_rowcnt[t] = 0; g_rowcur[t] = 0; }
    if (t < PP) { g_cnt[t] = 0; g_cur[t] = 0; }
}

__global__ void k_hist(const int* __restrict__ ei, const int* __restrict__ et) {
    int e = blockIdx.x*blockDim.x + threadIdx.x;
    if (e >= EE) return;
    atomicAdd(&g_cnt[et[e]], 1);
    atomicAdd(&g_rowcnt[ei[e]], 1);
    atomicAdd(&g_rowcnt[ei[EE + e]], 1);
}

__global__ void __launch_bounds__(1024) k_scan() {
    __shared__ int sm[1024];
    int tid = threadIdx.x;
    int v = (tid < NN) ? g_rowcnt[tid] : 0;
    sm[tid] = v;
    __syncthreads();
    #pragma unroll
    for (int off = 1; off < 1024; off <<= 1) {
        int t = (tid >= off) ? sm[tid - off] : 0;
        __syncthreads();
        sm[tid] += t;
        __syncthreads();
    }
    if (tid < NN) g_rowoff[tid] = sm[tid] - v;
    if (tid == NN - 1) g_rowoff[NN] = sm[tid];
    if (tid == 0) {
        int a = 0;
        for (int p = 0; p < PP; p++) { g_off[p] = a; a += g_cnt[p]; }
        g_off[PP] = a;
    }
}

__global__ void k_bucket(const int* __restrict__ ei, const int* __restrict__ et) {
    int e = blockIdx.x*blockDim.x + threadIdx.x;
    if (e >= EE) return;
    int p = et[e];
    g_bucket[g_off[p] + atomicAdd(&g_cur[p], 1)] = e;
    int s = ei[e], d = ei[EE + e];
    g_rentry[g_rowoff[s] + atomicAdd(&g_rowcur[s], 1)] = e*2;       // row s, neighbor = dst
    g_rentry[g_rowoff[d] + atomicAdd(&g_rowcur[d], 1)] = e*2 + 1;   // row d, neighbor = src
}

// ---------------- fused change-of-basis weights, coalesced tiled form ----------------
__global__ void __launch_bounds__(192) k_pre_node(const float* __restrict__ Wnode,
                                                  const float* __restrict__ cobn) {
    int t  = blockIdx.x & 3;
    int f0 = (blockIdx.x >> 2) * 16;
    int tid = threadIdx.x;   // 192
    __shared__ float Ws[INODE][17];
    for (int j = tid; j < 16*INODE; j += 192) {
        int f = j / INODE, i = j % INODE;
        Ws[i][f] = Wnode[(t*FF + f0 + f)*INODE + i];
    }
    for (int j = tid; j < 16*3; j += 192)
        g_Wn[(t*FF + f0 + j/3)*WNS + IEDGE + (j % 3)] = 0.f;
    __syncthreads();
    if (tid >= IEDGE) return;
    float acc[16];
    #pragma unroll
    for (int f = 0; f < 16; f++) acc[f] = 0.f;
    for (int i = 0; i < INODE; i++) {
        float cv = cobn[(t*INODE + i)*IEDGE + tid];
        #pragma unroll
        for (int f = 0; f < 16; f++) acc[f] += cv * Ws[i][f];
    }
    #pragma unroll
    for (int f = 0; f < 16; f++) g_Wn[(t*FF + f0 + f)*WNS + tid] = acc[f];
}

__global__ void __launch_bounds__(192) k_pre_edge(const float* __restrict__ Wedge,
                                                  const float* __restrict__ cobe) {
    int p  = blockIdx.x >> 2;
    int k0 = (blockIdx.x & 3) * 16;
    int tid = threadIdx.x;   // 192
    __shared__ float Ws[IEDGE][17];
    for (int j = tid; j < 16*IEDGE; j += 192) {
        int k = j / IEDGE, i = j % IEDGE;
        Ws[i][k] = Wedge[(p*KK + k0 + k)*IEDGE + i];
    }
    __syncthreads();
    if (tid >= IEDGE) return;
    float acc[16];
    #pragma unroll
    for (int k = 0; k < 16; k++) acc[k] = 0.f;
    for (int i = 0; i < IEDGE; i++) {
        float cv = cobe[((size_t)p*IEDGE + i)*IEDGE + tid];
        #pragma unroll
        for (int k = 0; k < 16; k++) acc[k] += cv * Ws[i][k];
    }
    float4* dst = (float4*)&g_WcT[(p*IEDGE + tid)*KK + k0];
    #pragma unroll
    for (int k4 = 0; k4 < 4; k4++)
        dst[k4] = make_float4(acc[4*k4], acc[4*k4+1], acc[4*k4+2], acc[4*k4+3]);
}

// ---------------- node prep: m = nf@Wmsg, base = nf + na@Wattr ----------------
__global__ void k_node_prep(const float* __restrict__ nf, const float* __restrict__ na,
                            const float* __restrict__ Wmsg, const float* __restrict__ Wattr) {
    int n = blockIdx.x;
    int f = threadIdx.x;   // 128
    int gt = n*FF + f;
    __shared__ float row[FF];
    row[f] = nf[gt];
    __syncthreads();
    float a0 = 0.f, a1 = 0.f, a2 = 0.f, a3 = 0.f;
    #pragma unroll 4
    for (int g = 0; g < FF; g += 4) {
        a0 += row[g]   * Wmsg[(g)*FF + f];
        a1 += row[g+1] * Wmsg[(g+1)*FF + f];
        a2 += row[g+2] * Wmsg[(g+2)*FF + f];
        a3 += row[g+3] * Wmsg[(g+3)*FF + f];
    }
    g_m[gt] = (a0 + a1) + (a2 + a3);
    float b = row[f];
    #pragma unroll
    for (int t = 0; t < TT; t++) b += na[n*TT + t] * Wattr[t*FF + f];
    g_base[gt] = b;
}

// ---------------- gather aggregation, chain-free ----------------
__global__ void __launch_bounds__(128) k_gather(const int* __restrict__ ei) {
    int n = blockIdx.x;
    int tid = threadIdx.x;   // 128
    __shared__ int others[512];
    int lo = g_rowoff[n], cnt = g_rowoff[n+1] - lo;
    for (int q = tid; q < cnt; q += 128) {
        int v = g_rentry[lo + q];
        int e = v >> 1;
        others[q] = ((v & 1) ? ei[e] : ei[EE + e]) * FF;
    }
    __syncthreads();
    float a0 = 0.f, a1 = 0.f, a2 = 0.f, a3 = 0.f;
    int q = 0;
    for (; q + 4 <= cnt; q += 4) {
        a0 += g_m[others[q]   + tid];
        a1 += g_m[others[q+1] + tid];
        a2 += g_m[others[q+2] + tid];
        a3 += g_m[others[q+3] + tid];
    }
    for (; q < cnt; q++) a0 += g_m[others[q] + tid];
    g_nh[n*FF + tid] = g_base[n*FF + tid] + (a0 + a1 + a2 + a3) * 0.05f;
}

// ---------------- per-node outputs, 8 nodes per CTA ----------------
__global__ void __launch_bounds__(160) k_node_out(const float* __restrict__ Wem,
                                                  const float* __restrict__ Wproj,
                                                  const int* __restrict__ ntype) {
    int nb  = blockIdx.x * NODES8;
    int tid = threadIdx.x;             // 160
    __shared__ float nh[NODES8][FF];
    __shared__ int types[NODES8];
    for (int i = tid; i < NODES8*FF; i += 160) nh[i >> 7][i & 127] = g_nh[nb*FF + i];
    if (tid < NODES8) types[tid] = ntype[nb + tid];
    __syncthreads();
    int o = tid;
    if (o >= 139) return;
    const float4* w4 = 0; int stride4 = 0, kind, c0;
    if (o < 32)      { c0 = o*4;        w4 = (const float4*)(Wem + c0);             stride4 = HH/4; kind = 0; }
    else if (o < 64) { c0 = (o-32)*4;   w4 = (const float4*)(Wem + FF*HH + c0);     stride4 = HH/4; kind = 1; }
    else if (o < 80) { c0 = (o-64)*4;   w4 = (const float4*)(Wproj + FF*KK + c0);   stride4 = KK/4; kind = 2; }
    else if (o < 96) { c0 = (o-80)*4;   w4 = (const float4*)(Wproj + 2*FF*KK + c0); stride4 = KK/4; kind = 3; }
    else             { c0 = (o-96)*4;   kind = 4; }
    float4 acc[NODES8];
    #pragma unroll
    for (int m = 0; m < NODES8; m++) acc[m] = make_float4(0.f,0.f,0.f,0.f);
    if (kind < 4) {
        #pragma unroll 4
        for (int g = 0; g < FF; g++) {
            float4 w = w4[g*stride4];
            #pragma unroll
            for (int m = 0; m < NODES8; m++) {
                float h = nh[m][g];
                acc[m].x += h*w.x; acc[m].y += h*w.y; acc[m].z += h*w.z; acc[m].w += h*w.w;
            }
        }
    } else {
        const float4* wn[NODES8];
        #pragma unroll
        for (int m = 0; m < NODES8; m++) wn[m] = (const float4*)(g_Wn + types[m]*FF*WNS + c0);
        for (int g = 0; g < FF; g++) {
            #pragma unroll
            for (int m = 0; m < NODES8; m++) {
                float4 w = wn[m][g*(WNS/4)];
                float h = nh[m][g];
                acc[m].x += h*w.x; acc[m].y += h*w.y; acc[m].z += h*w.z; acc[m].w += h*w.w;
            }
        }
    }
    #pragma unroll
    for (int m = 0; m < NODES8; m++) {
        int n = nb + m;
        if (kind == 0)      *(float4*)&g_r1[n*HH + c0] = acc[m];
        else if (kind == 1) *(float4*)&g_r2[n*HH + c0] = acc[m];
        else if (kind == 2) *(float4*)&g_q1[n*KK + c0] = acc[m];
        else if (kind == 3) *(float4*)&g_q2[n*KK + c0] = acc[m];
        else {
            float v[4] = {acc[m].x, acc[m].y, acc[m].z, acc[m].w};
            #pragma unroll
            for (int j = 0; j < 4; j++) {
                int xy = c0 + j;
                if (xy < IEDGE) g_nblk[n*IEDGE + xy] = v[j];
            }
        }
    }
}

// ---------------- per-edge: edge_msg -> u -> h_ij/h_ji ----------------
__global__ void __launch_bounds__(128) k_edge_msg(const float* __restrict__ ef, const float* __restrict__ ea,
                                                  const float* __restrict__ Wem, const float* __restrict__ Wproj,
                                                  const int* __restrict__ ei) {
    __shared__ __align__(16) float wp[KK*WPPAD];
    __shared__ __align__(16) float msg[4][HH];
    __shared__ float eatt[4][32];
    __shared__ int sd[8];
    int tid = threadIdx.x;   // 128
    float emreg[32];
    #pragma unroll
    for (int j = 0; j < 32; j++) emreg[j] = Wem[(2*FF + j)*HH + tid];
    for (int i = tid; i < FF*KK; i += 128) {
        int r = i >> 6, c = i & 63;
        wp[c*WPPAD + r] = Wproj[i];
    }
    __syncthreads();
    for (int grp = blockIdx.x; grp < EE/4; grp += gridDim.x) {
        int e0 = grp*4;
        {
            int el = tid >> 5, j = tid & 31;
            eatt[el][j] = (j < EAD) ? ef[(e0+el)*EAD + j] : ea[(e0+el)*EAD + (j - EAD)];
        }
        if (tid < 8) sd[tid] = ei[(tid & 1)*EE + e0 + (tid >> 1)];
        __syncthreads();
        #pragma unroll
        for (int el = 0; el < 4; el++) {
            float fe = 0.f;
            #pragma unroll
            for (int j = 0; j < 32; j++) fe += eatt[el][j]*emreg[j];
            float pre = g_r1[sd[2*el]*HH + tid] + g_r2[sd[2*el+1]*HH + tid] + fe;
            float ex = __expf(2.f*pre);
            msg[el][tid] = 1.f - __fdividef(2.f, ex + 1.f);
        }
        __syncthreads();
        int c = tid & 63, hh = tid >> 6;
        const float4* wr = (const float4*)&wp[c*WPPAD];
        const float4* m0 = (const float4*)msg[2*hh];
        const float4* m1 = (const float4*)msg[2*hh + 1];
        float u0 = 0.f, u1 = 0.f;
        #pragma unroll 8
        for (int g = 0; g < HH/4; g++) {
            float4 w = wr[g]; float4 a = m0[g]; float4 b = m1[g];
            u0 += w.x*a.x + w.y*a.y + w.z*a.z + w.w*a.w;
            u1 += w.x*b.x + w.y*b.y + w.z*b.z + w.w*b.w;
        }
        #pragma unroll
        for (int q = 0; q < 2; q++) {
            int el = 2*hh + q;
            float u = q ? u1 : u0;
            int e = e0 + el, s = sd[2*el], d = sd[2*el + 1];
            g_h[e*2*KK + c]      = u + g_q1[s*KK + c] + g_q2[d*KK + c];
            g_h[e*2*KK + KK + c] = u + g_q1[d*KK + c] + g_q2[s*KK + c];
        }
        __syncthreads();
    }
}

// ---------------- per-edge 13x13 blocks -> atomic scatter into zeroed M (+ diag blocks) ----------------
__global__ void k_edge_blocks(const int* __restrict__ ei, float* __restrict__ M) {
    int p   = blockIdx.y;
    int tid = threadIdx.x;   // 192
    if (p == PP) {           // diagonal node blocks
        int n0 = blockIdx.x * 16;
        int n1 = min(n0 + 16, NN);
        for (int n = n0; n < n1; n++)
            for (int j = tid; j < IEDGE; j += 192) {
                int x = j/DD, y = j - x*DD;
                atomicAdd(&M[(size_t)(n*DD + x)*NDIM + n*DD + y], g_nblk[n*IEDGE + j]);
            }
        return;
    }
    __shared__ __align__(16) float wc[IEDGE*WCPAD];
    __shared__ __align__(16) float hsm[4*2*KK];
    __shared__ int einfo[8];
    int beg = g_off[p], end = g_off[p+1];
    int cnt = end - beg;
    int per = (cnt + gridDim.x - 1) / gridDim.x;
    int lo  = beg + blockIdx.x * per;
    int hi  = min(lo + per, end);
    if (lo >= hi) return;
    const float* srcw = g_WcT + p*IEDGE*KK;
    for (int i = tid; i < IEDGE*(KK/4); i += blockDim.x) {
        int xy = i >> 4, kk = i & 15;
        ((float4*)(wc + xy*WCPAD))[kk] = ((const float4*)(srcw + xy*KK))[kk];
    }
    __syncthreads();
    int x = 0, y = 0, xyt = 0;
    if (tid < IEDGE) { x = tid/DD; y = tid - x*DD; xyt = y*DD + x; }
    for (int base = lo; base < hi; base += 4) {
        int ne = min(4, hi - base);
        for (int i = tid; i < 4*2*KK; i += blockDim.x) {
            int el = i >> 7, off = i & 127;
            float v = 0.f;
            if (el < ne) v = g_h[(size_t)g_bucket[base + el]*2*KK + off];
            hsm[i] = v;
        }
        if (tid < 8) {
            int el = tid >> 1;
            int e = g_bucket[base + min(el, ne - 1)];
            einfo[tid] = ei[(tid & 1)*EE + e];
        }
        __syncthreads();
        if (tid < IEDGE) {
            const float4* wf = (const float4*)(wc + tid*WCPAD);
            const float4* wt = (const float4*)(wc + xyt*WCPAD);
            const float4* h4 = (const float4*)hsm;
            float a[4] = {0.f,0.f,0.f,0.f}, b[4] = {0.f,0.f,0.f,0.f};
            #pragma unroll
            for (int kk = 0; kk < KK/4; kk++) {
                float4 f = wf[kk], t = wt[kk];
                #pragma unroll
                for (int el = 0; el < 4; el++) {
                    float4 hf = h4[el*32 + kk];
                    float4 hb = h4[el*32 + 16 + kk];
                    a[el] += hf.x*f.x + hf.y*f.y + hf.z*f.z + hf.w*f.w;
                    b[el] += hb.x*t.x + hb.y*t.y + hb.z*t.z + hb.w*t.w;
                }
            }
            #pragma unroll
            for (int el = 0; el < 4; el++) {
                if (el < ne) {
                    float v = 0.5f*(a[el] + b[el]);
                    int s = einfo[2*el], d = einfo[2*el + 1];
                    atomicAdd(&M[(size_t)(s*DD + x)*NDIM + d*DD + y], v);
                    atomicAdd(&M[(size_t)(d*DD + y)*NDIM + s*DD + x], v);
                }
            }
        }
        __syncthreads();
    }
}

// ---------------- launcher: fork-join graph; resources created once on call 1 ----------------
extern "C" void kernel_launch(void* const* d_in, const int* in_sizes, int n_in,
                              void* d_out, int out_size) {
    const float* nf    = (const float*)d_in[0];
    const float* na    = (const float*)d_in[1];
    const float* ef    = (const float*)d_in[2];
    const float* ea    = (const float*)d_in[3];
    const int*   ei    = (const int*)d_in[4];
    const int*   ntype = (const int*)d_in[5];
    const int*   etype = (const int*)d_in[6];
    const float* Wmsg  = (const float*)d_in[7];
    const float* Wattr = (const float*)d_in[8];
    const float* Wem   = (const float*)d_in[9];
    const float* Wproj = (const float*)d_in[10];
    const float* Wnode = (const float*)d_in[11];
    const float* Wedge = (const float*)d_in[12];
    const float* cobn  = (const float*)d_in[13];
    const float* cobe  = (const float*)d_in[14];
    float* M = (float*)d_out;

    static cudaStream_t s1 = 0, s2 = 0;
    static cudaEvent_t evF = 0, evZ = 0, evB = 0, evW = 0;
    if (!s1) {   // first call = non-captured correctness run: safe init point
        cudaStreamCreateWithFlags(&s1, cudaStreamNonBlocking);
        cudaStreamCreateWithFlags(&s2, cudaStreamNonBlocking);
        cudaEventCreateWithFlags(&evF, cudaEventDisableTiming);
        cudaEventCreateWithFlags(&evZ, cudaEventDisableTiming);
        cudaEventCreateWithFlags(&evB, cudaEventDisableTiming);
        cudaEventCreateWithFlags(&evW, cudaEventDisableTiming);
    }

    // fork
    cudaEventRecord(evF, 0);
    cudaStreamWaitEvent(s1, evF, 0);
    cudaStreamWaitEvent(s2, evF, 0);

    // branch 2 head: index pipeline (issued first so k_zero_tma lands in the profiled slot)
    k_zero_cnt<<<1, 1024, 0, s2>>>();
    k_hist<<<(EE + 255)/256, 256, 0, s2>>>(ei, etype);
    k_scan<<<1, 1024, 0, s2>>>();

    // branch 1: zero 676MB via TMA bulk stores — 3 CTAs/SM to saturate per-SM TMA service
    k_zero_tma<<<444, 256, 0, s1>>>((char*)M);
    cudaEventRecord(evZ, s1);

    // branch 2 tail
    k_bucket<<<(EE + 255)/256, 256, 0, s2>>>(ei, etype);
    cudaEventRecord(evB, s2);
    k_pre_node<<<32, 192, 0, s2>>>(Wnode, cobn);
    k_pre_edge<<<40, 192, 0, s2>>>(Wedge, cobe);
    cudaEventRecord(evW, s2);

    // main chain
    k_node_prep<<<NN, FF>>>(nf, na, Wmsg, Wattr);
    cudaStreamWaitEvent(0, evB, 0);
    k_gather<<<NN, 128>>>(ei);
    cudaStreamWaitEvent(0, evW, 0);
    k_node_out<<<NN/NODES8, 160>>>(Wem, Wproj, ntype);
    k_edge_msg<<<1480, 128>>>(ef, ea, Wem, Wproj, ei);
    cudaStreamWaitEvent(0, evZ, 0);
    k_edge_blocks<<<dim3(64, PP+1), 192>>>(ei, M);
}

// round 12
// speedup vs baseline: 1.2160x; 1.0365x over previous
#include <cuda_runtime.h>
#include <math.h>
#include <stdint.h>

#define NN 1000
#define FF 128
#define TT 4
#define PP 10
#define DD 13
#define EE 20000
#define EAD 16
#define HH 128
#define KK 64
#define NDIM 13000        // N*D
#define IEDGE 169
#define INODE 91
#define WNS 172           // padded Wn row stride (mult of 4)
#define WCPAD 68          // padded Wc smem row stride
#define WPPAD 132         // padded Wp smem row stride
#define NODES8 8

#define ZCH  32768u       // TMA chunk
#define NFULL 20629u      // full chunks
#define TAILB 28928u      // remainder bytes (676e6 - 20629*32768), mult of 16

// ---------------- scratch (device globals; no runtime allocation) ----------------
__device__ __align__(16) float g_m[NN*FF];
__device__ float g_base[NN*FF];
__device__ float g_nh[NN*FF];
__device__ float g_r1[NN*HH];
__device__ float g_r2[NN*HH];
__device__ float g_q1[NN*KK];
__device__ float g_q2[NN*KK];
__device__ __align__(16) float g_Wn[TT*FF*WNS];
__device__ __align__(16) float g_WcT[PP*IEDGE*KK];
__device__ __align__(16) float g_h[EE*2*KK];        // per-edge [h_ij(64) | h_ji(64)]
__device__ float g_nblk[NN*IEDGE];                  // node diagonal blocks
__device__ int   g_cnt[PP];
__device__ int   g_off[PP+1];
__device__ int   g_cur[PP];
__device__ int   g_rowcnt[NN];
__device__ int   g_rowoff[NN+1];
__device__ int   g_rowcur[NN];
__device__ int   g_bucket[EE];
__device__ int   g_rentry[2*EE];                    // e*2 | flag (flag=1 -> neighbor is src)

// ---------------- zero M via TMA bulk stores; 3 CTAs/SM (measured 105us @74% DRAM) ----------------
__global__ void __launch_bounds__(256) k_zero_tma(char* __restrict__ M) {
    __shared__ __align__(128) float4 zbuf[ZCH/16];   // 32KB of zeros
    int tid = threadIdx.x;
    float4 z = make_float4(0.f, 0.f, 0.f, 0.f);
    #pragma unroll
    for (int i = 0; i < (int)(ZCH/16/256); i++) zbuf[tid + i*256] = z;
    __syncthreads();
    if (tid != 0) return;
    asm volatile("fence.proxy.async.shared::cta;" ::: "memory");
    uint32_t saddr;
    asm("{ .reg .u64 t; cvta.to.shared.u64 t, %1; cvt.u32.u64 %0, t; }" : "=r"(saddr) : "l"(zbuf));
    for (uint32_t c = blockIdx.x; c < NFULL + 1; c += gridDim.x) {
        char* dst = M + (size_t)c * ZCH;
        uint32_t bytes = (c == NFULL) ? TAILB : ZCH;
        asm volatile("cp.async.bulk.global.shared::cta.bulk_group [%0], [%1], %2;"
                     :: "l"(dst), "r"(saddr), "r"(bytes) : "memory");
    }
    asm volatile("cp.async.bulk.commit_group;" ::: "memory");
    asm volatile("cp.async.bulk.wait_group 0;" ::: "memory");
}

// ---------------- index pipeline (side stream) ----------------
__global__ void k_zero_cnt() {
    int t = threadIdx.x;   // 1024
    if (t < NN) { g_rowcnt[t] = 0; g_rowcur[t] = 0; }
    if (t < PP) { g_cnt[t] = 0; g_cur[t] = 0; }
}

__global__ void k_hist(const int* __restrict__ ei, const int* __restrict__ et) {
    int e = blockIdx.x*blockDim.x + threadIdx.x;
    if (e >= EE) return;
    atomicAdd(&g_cnt[et[e]], 1);
    atomicAdd(&g_rowcnt[ei[e]], 1);
    atomicAdd(&g_rowcnt[ei[EE + e]], 1);
}

__global__ void __launch_bounds__(1024) k_scan() {
    __shared__ int sm[1024];
    int tid = threadIdx.x;
    int v = (tid < NN) ? g_rowcnt[tid] : 0;
    sm[tid] = v;
    __syncthreads();
    #pragma unroll
    for (int off = 1; off < 1024; off <<= 1) {
        int t = (tid >= off) ? sm[tid - off] : 0;
        __syncthreads();
        sm[tid] += t;
        __syncthreads();
    }
    if (tid < NN) g_rowoff[tid] = sm[tid] - v;
    if (tid == NN - 1) g_rowoff[NN] = sm[tid];
    if (tid == 0) {
        int a = 0;
        for (int p = 0; p < PP; p++) { g_off[p] = a; a += g_cnt[p]; }
        g_off[PP] = a;
    }
}

__global__ void k_bucket(const int* __restrict__ ei, const int* __restrict__ et) {
    int e = blockIdx.x*blockDim.x + threadIdx.x;
    if (e >= EE) return;
    int p = et[e];
    g_bucket[g_off[p] + atomicAdd(&g_cur[p], 1)] = e;
    int s = ei[e], d = ei[EE + e];
    g_rentry[g_rowoff[s] + atomicAdd(&g_rowcur[s], 1)] = e*2;       // row s, neighbor = dst
    g_rentry[g_rowoff[d] + atomicAdd(&g_rowcur[d], 1)] = e*2 + 1;   // row d, neighbor = src
}

// ---------------- fused change-of-basis weights, coalesced tiled form ----------------
__global__ void __launch_bounds__(192) k_pre_node(const float* __restrict__ Wnode,
                                                  const float* __restrict__ cobn) {
    int t  = blockIdx.x & 3;
    int f0 = (blockIdx.x >> 2) * 16;
    int tid = threadIdx.x;   // 192
    __shared__ float Ws[INODE][17];
    for (int j = tid; j < 16*INODE; j += 192) {
        int f = j / INODE, i = j % INODE;
        Ws[i][f] = Wnode[(t*FF + f0 + f)*INODE + i];
    }
    for (int j = tid; j < 16*3; j += 192)
        g_Wn[(t*FF + f0 + j/3)*WNS + IEDGE + (j % 3)] = 0.f;
    __syncthreads();
    if (tid >= IEDGE) return;
    float acc[16];
    #pragma unroll
    for (int f = 0; f < 16; f++) acc[f] = 0.f;
    for (int i = 0; i < INODE; i++) {
        float cv = cobn[(t*INODE + i)*IEDGE + tid];
        #pragma unroll
        for (int f = 0; f < 16; f++) acc[f] += cv * Ws[i][f];
    }
    #pragma unroll
    for (int f = 0; f < 16; f++) g_Wn[(t*FF + f0 + f)*WNS + tid] = acc[f];
}

__global__ void __launch_bounds__(192) k_pre_edge(const float* __restrict__ Wedge,
                                                  const float* __restrict__ cobe) {
    int p  = blockIdx.x >> 2;
    int k0 = (blockIdx.x & 3) * 16;
    int tid = threadIdx.x;   // 192
    __shared__ float Ws[IEDGE][17];
    for (int j = tid; j < 16*IEDGE; j += 192) {
        int k = j / IEDGE, i = j % IEDGE;
        Ws[i][k] = Wedge[(p*KK + k0 + k)*IEDGE + i];
    }
    __syncthreads();
    if (tid >= IEDGE) return;
    float acc[16];
    #pragma unroll
    for (int k = 0; k < 16; k++) acc[k] = 0.f;
    for (int i = 0; i < IEDGE; i++) {
        float cv = cobe[((size_t)p*IEDGE + i)*IEDGE + tid];
        #pragma unroll
        for (int k = 0; k < 16; k++) acc[k] += cv * Ws[i][k];
    }
    float4* dst = (float4*)&g_WcT[(p*IEDGE + tid)*KK + k0];
    #pragma unroll
    for (int k4 = 0; k4 < 4; k4++)
        dst[k4] = make_float4(acc[4*k4], acc[4*k4+1], acc[4*k4+2], acc[4*k4+3]);
}

// ---------------- node prep: m = nf@Wmsg, base = nf + na@Wattr ----------------
__global__ void k_node_prep(const float* __restrict__ nf, const float* __restrict__ na,
                            const float* __restrict__ Wmsg, const float* __restrict__ Wattr) {
    int n = blockIdx.x;
    int f = threadIdx.x;   // 128
    int gt = n*FF + f;
    __shared__ float row[FF];
    row[f] = nf[gt];
    __syncthreads();
    float a0 = 0.f, a1 = 0.f, a2 = 0.f, a3 = 0.f;
    #pragma unroll 4
    for (int g = 0; g < FF; g += 4) {
        a0 += row[g]   * Wmsg[(g)*FF + f];
        a1 += row[g+1] * Wmsg[(g+1)*FF + f];
        a2 += row[g+2] * Wmsg[(g+2)*FF + f];
        a3 += row[g+3] * Wmsg[(g+3)*FF + f];
    }
    g_m[gt] = (a0 + a1) + (a2 + a3);
    float b = row[f];
    #pragma unroll
    for (int t = 0; t < TT; t++) b += na[n*TT + t] * Wattr[t*FF + f];
    g_base[gt] = b;
}

// ---------------- gather aggregation, chain-free ----------------
__global__ void __launch_bounds__(128) k_gather(const int* __restrict__ ei) {
    int n = blockIdx.x;
    int tid = threadIdx.x;   // 128
    __shared__ int others[512];
    int lo = g_rowoff[n], cnt = g_rowoff[n+1] - lo;
    for (int q = tid; q < cnt; q += 128) {
        int v = g_rentry[lo + q];
        int e = v >> 1;
        others[q] = ((v & 1) ? ei[e] : ei[EE + e]) * FF;
    }
    __syncthreads();
    float a0 = 0.f, a1 = 0.f, a2 = 0.f, a3 = 0.f;
    int q = 0;
    for (; q + 4 <= cnt; q += 4) {
        a0 += g_m[others[q]   + tid];
        a1 += g_m[others[q+1] + tid];
        a2 += g_m[others[q+2] + tid];
        a3 += g_m[others[q+3] + tid];
    }
    for (; q < cnt; q++) a0 += g_m[others[q] + tid];
    g_nh[n*FF + tid] = g_base[n*FF + tid] + (a0 + a1 + a2 + a3) * 0.05f;
}

// ---------------- per-node outputs, 8 nodes per CTA ----------------
__global__ void __launch_bounds__(160) k_node_out(const float* __restrict__ Wem,
                                                  const float* __restrict__ Wproj,
                                                  const int* __restrict__ ntype) {
    int nb  = blockIdx.x * NODES8;
    int tid = threadIdx.x;             // 160
    __shared__ float nh[NODES8][FF];
    __shared__ int types[NODES8];
    for (int i = tid; i < NODES8*FF; i += 160) nh[i >> 7][i & 127] = g_nh[nb*FF + i];
    if (tid < NODES8) types[tid] = ntype[nb + tid];
    __syncthreads();
    int o = tid;
    if (o >= 139) return;
    const float4* w4 = 0; int stride4 = 0, kind, c0;
    if (o < 32)      { c0 = o*4;        w4 = (const float4*)(Wem + c0);             stride4 = HH/4; kind = 0; }
    else if (o < 64) { c0 = (o-32)*4;   w4 = (const float4*)(Wem + FF*HH + c0);     stride4 = HH/4; kind = 1; }
    else if (o < 80) { c0 = (o-64)*4;   w4 = (const float4*)(Wproj + FF*KK + c0);   stride4 = KK/4; kind = 2; }
    else if (o < 96) { c0 = (o-80)*4;   w4 = (const float4*)(Wproj + 2*FF*KK + c0); stride4 = KK/4; kind = 3; }
    else             { c0 = (o-96)*4;   kind = 4; }
    float4 acc[NODES8];
    #pragma unroll
    for (int m = 0; m < NODES8; m++) acc[m] = make_float4(0.f,0.f,0.f,0.f);
    if (kind < 4) {
        #pragma unroll 4
        for (int g = 0; g < FF; g++) {
            float4 w = w4[g*stride4];
            #pragma unroll
            for (int m = 0; m < NODES8; m++) {
                float h = nh[m][g];
                acc[m].x += h*w.x; acc[m].y += h*w.y; acc[m].z += h*w.z; acc[m].w += h*w.w;
            }
        }
    } else {
        const float4* wn[NODES8];
        #pragma unroll
        for (int m = 0; m < NODES8; m++) wn[m] = (const float4*)(g_Wn + types[m]*FF*WNS + c0);
        for (int g = 0; g < FF; g++) {
            #pragma unroll
            for (int m = 0; m < NODES8; m++) {
                float4 w = wn[m][g*(WNS/4)];
                float h = nh[m][g];
                acc[m].x += h*w.x; acc[m].y += h*w.y; acc[m].z += h*w.z; acc[m].w += h*w.w;
            }
        }
    }
    #pragma unroll
    for (int m = 0; m < NODES8; m++) {
        int n = nb + m;
        if (kind == 0)      *(float4*)&g_r1[n*HH + c0] = acc[m];
        else if (kind == 1) *(float4*)&g_r2[n*HH + c0] = acc[m];
        else if (kind == 2) *(float4*)&g_q1[n*KK + c0] = acc[m];
        else if (kind == 3) *(float4*)&g_q2[n*KK + c0] = acc[m];
        else {
            float v[4] = {acc[m].x, acc[m].y, acc[m].z, acc[m].w};
            #pragma unroll
            for (int j = 0; j < 4; j++) {
                int xy = c0 + j;
                if (xy < IEDGE) g_nblk[n*IEDGE + xy] = v[j];
            }
        }
    }
}

// ---------------- per-edge: edge_msg -> u -> h_ij/h_ji ----------------
__global__ void __launch_bounds__(128) k_edge_msg(const float* __restrict__ ef, const float* __restrict__ ea,
                                                  const float* __restrict__ Wem, const float* __restrict__ Wproj,
                                                  const int* __restrict__ ei) {
    __shared__ __align__(16) float wp[KK*WPPAD];
    __shared__ __align__(16) float msg[4][HH];
    __shared__ float eatt[4][32];
    __shared__ int sd[8];
    int tid = threadIdx.x;   // 128
    float emreg[32];
    #pragma unroll
    for (int j = 0; j < 32; j++) emreg[j] = Wem[(2*FF + j)*HH + tid];
    for (int i = tid; i < FF*KK; i += 128) {
        int r = i >> 6, c = i & 63;
        wp[c*WPPAD + r] = Wproj[i];
    }
    __syncthreads();
    for (int grp = blockIdx.x; grp < EE/4; grp += gridDim.x) {
        int e0 = grp*4;
        {
            int el = tid >> 5, j = tid & 31;
            eatt[el][j] = (j < EAD) ? ef[(e0+el)*EAD + j] : ea[(e0+el)*EAD + (j - EAD)];
        }
        if (tid < 8) sd[tid] = ei[(tid & 1)*EE + e0 + (tid >> 1)];
        __syncthreads();
        #pragma unroll
        for (int el = 0; el < 4; el++) {
            float fe = 0.f;
            #pragma unroll
            for (int j = 0; j < 32; j++) fe += eatt[el][j]*emreg[j];
            float pre = g_r1[sd[2*el]*HH + tid] + g_r2[sd[2*el+1]*HH + tid] + fe;
            float ex = __expf(2.f*pre);
            msg[el][tid] = 1.f - __fdividef(2.f, ex + 1.f);
        }
        __syncthreads();
        int c = tid & 63, hh = tid >> 6;
        const float4* wr = (const float4*)&wp[c*WPPAD];
        const float4* m0 = (const float4*)msg[2*hh];
        const float4* m1 = (const float4*)msg[2*hh + 1];
        float u0 = 0.f, u1 = 0.f;
        #pragma unroll 8
        for (int g = 0; g < HH/4; g++) {
            float4 w = wr[g]; float4 a = m0[g]; float4 b = m1[g];
            u0 += w.x*a.x + w.y*a.y + w.z*a.z + w.w*a.w;
            u1 += w.x*b.x + w.y*b.y + w.z*b.z + w.w*b.w;
        }
        #pragma unroll
        for (int q = 0; q < 2; q++) {
            int el = 2*hh + q;
            float u = q ? u1 : u0;
            int e = e0 + el, s = sd[2*el], d = sd[2*el + 1];
            g_h[e*2*KK + c]      = u + g_q1[s*KK + c] + g_q2[d*KK + c];
            g_h[e*2*KK + KK + c] = u + g_q1[d*KK + c] + g_q2[s*KK + c];
        }
        __syncthreads();
    }
}

// ---------------- per-edge 13x13 blocks -> atomic scatter into zeroed M (+ diag blocks) ----------------
__global__ void k_edge_blocks(const int* __restrict__ ei, float* __restrict__ M) {
    int p   = blockIdx.y;
    int tid = threadIdx.x;   // 192
    if (p == PP) {           // diagonal node blocks
        int n0 = blockIdx.x * 7;
        int n1 = min(n0 + 7, NN);
        for (int n = n0; n < n1; n++)
            for (int j = tid; j < IEDGE; j += 192) {
                int x = j/DD, y = j - x*DD;
                atomicAdd(&M[(size_t)(n*DD + x)*NDIM + n*DD + y], g_nblk[n*IEDGE + j]);
            }
        return;
    }
    __shared__ __align__(16) float wc[IEDGE*WCPAD];
    __shared__ __align__(16) float hsm[4*2*KK];
    __shared__ int einfo[8];
    int beg = g_off[p], end = g_off[p+1];
    int cnt = end - beg;
    int per = (cnt + gridDim.x - 1) / gridDim.x;
    int lo  = beg + blockIdx.x * per;
    int hi  = min(lo + per, end);
    if (lo >= hi) return;
    const float* srcw = g_WcT + p*IEDGE*KK;
    for (int i = tid; i < IEDGE*(KK/4); i += blockDim.x) {
        int xy = i >> 4, kk = i & 15;
        ((float4*)(wc + xy*WCPAD))[kk] = ((const float4*)(srcw + xy*KK))[kk];
    }
    __syncthreads();
    int x = 0, y = 0, xyt = 0;
    if (tid < IEDGE) { x = tid/DD; y = tid - x*DD; xyt = y*DD + x; }
    for (int base = lo; base < hi; base += 4) {
        int ne = min(4, hi - base);
        for (int i = tid; i < 4*2*KK; i += blockDim.x) {
            int el = i >> 7, off = i & 127;
            float v = 0.f;
            if (el < ne) v = g_h[(size_t)g_bucket[base + el]*2*KK + off];
            hsm[i] = v;
        }
        if (tid < 8) {
            int el = tid >> 1;
            int e = g_bucket[base + min(el, ne - 1)];
            einfo[tid] = ei[(tid & 1)*EE + e];
        }
        __syncthreads();
        if (tid < IEDGE) {
            const float4* wf = (const float4*)(wc + tid*WCPAD);
            const float4* wt = (const float4*)(wc + xyt*WCPAD);
            const float4* h4 = (const float4*)hsm;
            float a[4] = {0.f,0.f,0.f,0.f}, b[4] = {0.f,0.f,0.f,0.f};
            #pragma unroll
            for (int kk = 0; kk < KK/4; kk++) {
                float4 f = wf[kk], t = wt[kk];
                #pragma unroll
                for (int el = 0; el < 4; el++) {
                    float4 hf = h4[el*32 + kk];
                    float4 hb = h4[el*32 + 16 + kk];
                    a[el] += hf.x*f.x + hf.y*f.y + hf.z*f.z + hf.w*f.w;
                    b[el] += hb.x*t.x + hb.y*t.y + hb.z*t.z + hb.w*t.w;
                }
            }
            #pragma unroll
            for (int el = 0; el < 4; el++) {
                if (el < ne) {
                    float v = 0.5f*(a[el] + b[el]);
                    int s = einfo[2*el], d = einfo[2*el + 1];
                    atomicAdd(&M[(size_t)(s*DD + x)*NDIM + d*DD + y], v);
                    atomicAdd(&M[(size_t)(d*DD + y)*NDIM + s*DD + x], v);
                }
            }
        }
        __syncthreads();
    }
}

// ---------------- launcher: ALL work on explicit non-blocking streams (no legacy-stream
// serialization); NULL stream only forks entry and joins exit ----------------
extern "C" void kernel_launch(void* const* d_in, const int* in_sizes, int n_in,
                              void* d_out, int out_size) {
    const float* nf    = (const float*)d_in[0];
    const float* na    = (const float*)d_in[1];
    const float* ef    = (const float*)d_in[2];
    const float* ea    = (const float*)d_in[3];
    const int*   ei    = (const int*)d_in[4];
    const int*   ntype = (const int*)d_in[5];
    const int*   etype = (const int*)d_in[6];
    const float* Wmsg  = (const float*)d_in[7];
    const float* Wattr = (const float*)d_in[8];
    const float* Wem   = (const float*)d_in[9];
    const float* Wproj = (const float*)d_in[10];
    const float* Wnode = (const float*)d_in[11];
    const float* Wedge = (const float*)d_in[12];
    const float* cobn  = (const float*)d_in[13];
    const float* cobe  = (const float*)d_in[14];
    float* M = (float*)d_out;

    static cudaStream_t s0 = 0, s1 = 0, s2 = 0;
    static cudaEvent_t evF = 0, evZ = 0, evB = 0, evW = 0, evE = 0;
    if (!s0) {   // first call = non-captured correctness run: safe init point
        cudaStreamCreateWithFlags(&s0, cudaStreamNonBlocking);
        cudaStreamCreateWithFlags(&s1, cudaStreamNonBlocking);
        cudaStreamCreateWithFlags(&s2, cudaStreamNonBlocking);
        cudaEventCreateWithFlags(&evF, cudaEventDisableTiming);
        cudaEventCreateWithFlags(&evZ, cudaEventDisableTiming);
        cudaEventCreateWithFlags(&evB, cudaEventDisableTiming);
        cudaEventCreateWithFlags(&evW, cudaEventDisableTiming);
        cudaEventCreateWithFlags(&evE, cudaEventDisableTiming);
    }

    // fork from the capture (NULL) stream
    cudaEventRecord(evF, 0);
    cudaStreamWaitEvent(s0, evF, 0);
    cudaStreamWaitEvent(s1, evF, 0);
    cudaStreamWaitEvent(s2, evF, 0);

    // branch 1: zero 676MB via TMA bulk stores (measured 105us @ 74% DRAM)
    k_zero_tma<<<444, 256, 0, s1>>>((char*)M);
    cudaEventRecord(evZ, s1);

    // branch 2: index pipeline, then fused change-of-basis weights
    k_zero_cnt<<<1, 1024, 0, s2>>>();
    k_hist<<<(EE + 255)/256, 256, 0, s2>>>(ei, etype);
    k_scan<<<1, 1024, 0, s2>>>();
    k_bucket<<<(EE + 255)/256, 256, 0, s2>>>(ei, etype);
    cudaEventRecord(evB, s2);
    k_pre_node<<<32, 192, 0, s2>>>(Wnode, cobn);
    k_pre_edge<<<40, 192, 0, s2>>>(Wedge, cobe);
    cudaEventRecord(evW, s2);

    // branch 0: main chain (explicit stream — no legacy-stream implicit sync)
    k_node_prep<<<NN, FF, 0, s0>>>(nf, na, Wmsg, Wattr);
    cudaStreamWaitEvent(s0, evB, 0);
    k_gather<<<NN, 128, 0, s0>>>(ei);
    cudaStreamWaitEvent(s0, evW, 0);
    k_node_out<<<NN/NODES8, 160, 0, s0>>>(Wem, Wproj, ntype);
    k_edge_msg<<<1480, 128, 0, s0>>>(ef, ea, Wem, Wproj, ei);
    cudaStreamWaitEvent(s0, evZ, 0);
    k_edge_blocks<<<dim3(160, PP+1), 192, 0, s0>>>(ei, M);
    cudaEventRecord(evE, s0);

    // join back to the capture (NULL) stream
    cudaStreamWaitEvent(0, evE, 0);
}